// round 12
// baseline (speedup 1.0000x reference)
#include <cuda_runtime.h>
#include <cuda_bf16.h>
#include <cstdint>

// Problem constants
#define S_LEN 4096
#define D_MODEL 2048
#define NH 16
#define NG 4
#define HD 128
#define KV_D (NG * HD)          // 512
#define QKV_N (D_MODEL + 2 * KV_D)  // 3072
#define SOFTMAX_SCALE 0.08838834764831845f  // 1/sqrt(128)

// bf16 hi/lo planes
__device__ __nv_bfloat16 g_xhi[S_LEN * D_MODEL];
__device__ __nv_bfloat16 g_xlo[S_LEN * D_MODEL];
__device__ __nv_bfloat16 g_qhi[S_LEN * D_MODEL];
__device__ __nv_bfloat16 g_qlo[S_LEN * D_MODEL];
__device__ __nv_bfloat16 g_khi[S_LEN * KV_D];
__device__ __nv_bfloat16 g_klo[S_LEN * KV_D];
__device__ __nv_bfloat16 g_vhi[S_LEN * KV_D];
__device__ __nv_bfloat16 g_vlo[S_LEN * KV_D];
__device__ __nv_bfloat16 g_ctxhi[S_LEN * D_MODEL];
__device__ __nv_bfloat16 g_ctxlo[S_LEN * D_MODEL];
__device__ __nv_bfloat16 g_wThi[QKV_N * D_MODEL];   // rows: 0-2047 Q, 2048-2559 K, 2560-3071 V
__device__ __nv_bfloat16 g_wTlo[QKV_N * D_MODEL];
__device__ __nv_bfloat16 g_woThi[D_MODEL * D_MODEL];
__device__ __nv_bfloat16 g_woTlo[D_MODEL * D_MODEL];

// ---------------------------------------------------------------------------
// Helpers
// ---------------------------------------------------------------------------
__device__ __forceinline__ uint32_t smem_to_u32(const void* p) {
    uint32_t a;
    asm("{ .reg .u64 t; cvta.to.shared.u64 t, %1; cvt.u32.u64 %0, t; }"
        : "=r"(a) : "l"(p));
    return a;
}

__device__ __forceinline__ void cp_async16(uint32_t smem_addr, const void* gptr) {
    asm volatile("cp.async.cg.shared.global [%0], [%1], 16;" :: "r"(smem_addr), "l"(gptr));
}
__device__ __forceinline__ void cp_async_commit() {
    asm volatile("cp.async.commit_group;" ::: "memory");
}
template <int N>
__device__ __forceinline__ void cp_async_wait() {
    asm volatile("cp.async.wait_group %0;" :: "n"(N) : "memory");
}

__device__ __forceinline__ uint32_t pack_bf16(float x, float y) {
    uint32_t r;
    asm("cvt.rn.bf16x2.f32 %0, %1, %2;" : "=r"(r) : "f"(y), "f"(x));
    return r;
}
__device__ __forceinline__ float bf16lo_f32(uint32_t h) { return __uint_as_float(h << 16); }
__device__ __forceinline__ float bf16hi_f32(uint32_t h) { return __uint_as_float(h & 0xffff0000u); }

__device__ __forceinline__ void split_bf16(float2 f, uint32_t& hi, uint32_t& lo) {
    hi = pack_bf16(f.x, f.y);
    float rx = f.x - bf16lo_f32(hi);
    float ry = f.y - bf16hi_f32(hi);
    lo = pack_bf16(rx, ry);
}

__device__ __forceinline__ void mma_bf16(float* c, const uint32_t* a, const uint32_t* b) {
    asm volatile(
        "mma.sync.aligned.m16n8k16.row.col.f32.bf16.bf16.f32 "
        "{%0,%1,%2,%3}, {%4,%5,%6,%7}, {%8,%9}, {%0,%1,%2,%3};"
        : "+f"(c[0]), "+f"(c[1]), "+f"(c[2]), "+f"(c[3])
        : "r"(a[0]), "r"(a[1]), "r"(a[2]), "r"(a[3]), "r"(b[0]), "r"(b[1]));
}

__device__ __forceinline__ void ldsm_x4(uint32_t* r, uint32_t addr) {
    asm volatile("ldmatrix.sync.aligned.m8n8.x4.shared.b16 {%0,%1,%2,%3}, [%4];"
        : "=r"(r[0]), "=r"(r[1]), "=r"(r[2]), "=r"(r[3]) : "r"(addr));
}
__device__ __forceinline__ void ldsm_x4t(uint32_t* r, uint32_t addr) {
    asm volatile("ldmatrix.sync.aligned.m8n8.x4.trans.shared.b16 {%0,%1,%2,%3}, [%4];"
        : "=r"(r[0]), "=r"(r[1]), "=r"(r[2]), "=r"(r[3]) : "r"(addr));
}

// rope one pair in fp32 then split to bf16 planes
__device__ __forceinline__ void rope_pair_store(
        float a, float b, int sg, int d, float scale,
        const float* __restrict__ cosp, const float* __restrict__ sinp,
        __nv_bfloat16* __restrict__ hi, __nv_bfloat16* __restrict__ lo, size_t obase) {
    float c1 = cosp[sg * 128 + d],      s1 = sinp[sg * 128 + d];
    float c2 = cosp[sg * 128 + d + 64], s2 = sinp[sg * 128 + d + 64];
    float o1 = (a * c1 - b * s1) * scale;
    float o2 = (b * c2 + a * s2) * scale;
    __nv_bfloat16 h1 = __float2bfloat16(o1);
    __nv_bfloat16 L1 = __float2bfloat16(o1 - __bfloat162float(h1));
    __nv_bfloat16 h2 = __float2bfloat16(o2);
    __nv_bfloat16 L2 = __float2bfloat16(o2 - __bfloat162float(h2));
    hi[obase] = h1;      lo[obase] = L1;
    hi[obase + 64] = h2; lo[obase + 64] = L2;
}

// ---------------------------------------------------------------------------
// Split kernels
// ---------------------------------------------------------------------------
__global__ void split_kernel(const float* __restrict__ in,
                             __nv_bfloat16* __restrict__ hi,
                             __nv_bfloat16* __restrict__ lo,
                             int n4) {
    int idx = blockIdx.x * blockDim.x + threadIdx.x;
    if (idx >= n4) return;
    float4 v = ((const float4*)in)[idx];
    uint32_t h01, l01, h23, l23;
    split_bf16(make_float2(v.x, v.y), h01, l01);
    split_bf16(make_float2(v.z, v.w), h23, l23);
    ((uint2*)hi)[idx] = make_uint2(h01, h23);
    ((uint2*)lo)[idx] = make_uint2(l01, l23);
}

__global__ void transpose_split_kernel(const float* __restrict__ in,
                                       __nv_bfloat16* __restrict__ hiT,
                                       __nv_bfloat16* __restrict__ loT,
                                       int R, int C) {
    __shared__ float t[32][33];
    int c0 = blockIdx.x * 32, r0 = blockIdx.y * 32;
    int x = threadIdx.x, y = threadIdx.y;
#pragma unroll
    for (int i = y; i < 32; i += 8) t[i][x] = in[(size_t)(r0 + i) * C + c0 + x];
    __syncthreads();
#pragma unroll
    for (int i = y; i < 32; i += 8) {
        float v = t[x][i];
        __nv_bfloat16 h = __float2bfloat16(v);
        __nv_bfloat16 l = __float2bfloat16(v - __bfloat162float(h));
        size_t o = (size_t)(c0 + i) * R + r0 + x;
        hiT[o] = h;
        loT[o] = l;
    }
}

#define SROWB 56

// ---------------------------------------------------------------------------
// Wide GEMM 128x256. Two modes:
//   C != null : plain fp32 store (O projection)
//   C == null : merged QKV epilogue selected by n0:
//       n0 < 2048          -> rope+scale+split to Q planes (ld 2048)
//       2048 <= n0 < 2560  -> rope+split to K planes (ld 512)
//       n0 >= 2560         -> plain split to V planes (ld 512)
// ---------------------------------------------------------------------------
#define WA_PL 14336
#define WB_PL 28672
#define WSTAGE_B 86016
#define GW_SMEM (2 * WSTAGE_B)   // 172032

__global__ __launch_bounds__(256, 1) void gemm_bf16p_wide(
        const __nv_bfloat16* __restrict__ Ahi, const __nv_bfloat16* __restrict__ Alo,
        const __nv_bfloat16* __restrict__ Bhi, const __nv_bfloat16* __restrict__ Blo,
        float* __restrict__ C,
        __nv_bfloat16* __restrict__ Qhi, __nv_bfloat16* __restrict__ Qlo,
        __nv_bfloat16* __restrict__ Khi, __nv_bfloat16* __restrict__ Klo,
        __nv_bfloat16* __restrict__ Vhi, __nv_bfloat16* __restrict__ Vlo,
        const float* __restrict__ cosp, const float* __restrict__ sinp,
        int M, int N, int K) {
    extern __shared__ char sm[];
    const uint32_t smem_u32 = smem_to_u32(sm);

    const int tid = threadIdx.x;
    const int wid = tid >> 5;
    const int lane = tid & 31;
    const int lr = lane & 7;
    const int lb8 = (lane >> 3) & 1;
    const int lb16 = (lane >> 4) & 1;
    const int wm = wid >> 2;
    const int wn = wid & 3;
    const int m0 = blockIdx.y * 128;
    const int n0 = blockIdx.x * 256;
    const int NS = K >> 5;

    auto load_stage = [&](int s, int buf) {
        const int k0 = s << 5;
        const uint32_t base = smem_u32 + buf * WSTAGE_B;
#pragma unroll
        for (int i = 0; i < 12; i++) {
            int c = tid + i * 256;
            if (c < 1024) {
                int pl = c >> 9;
                int idx = c & 511;
                int row = idx >> 2;
                int ch = idx & 3;
                const __nv_bfloat16* g = (pl ? Alo : Ahi) + (size_t)(m0 + row) * K + k0 + ch * 8;
                cp_async16(base + pl * WA_PL + (row * SROWB + ch * 8) * 2, g);
            } else {
                int cb = c - 1024;
                int pl = cb >> 10;
                int idx = cb & 1023;
                int row = idx >> 2;
                int ch = idx & 3;
                const __nv_bfloat16* g = (pl ? Blo : Bhi) + (size_t)(n0 + row) * K + k0 + ch * 8;
                cp_async16(base + 2 * WA_PL + pl * WB_PL + (row * SROWB + ch * 8) * 2, g);
            }
        }
    };

    float acc[4][8][4];
#pragma unroll
    for (int m = 0; m < 4; m++)
#pragma unroll
        for (int n = 0; n < 8; n++)
#pragma unroll
            for (int i = 0; i < 4; i++) acc[m][n][i] = 0.0f;

    load_stage(0, 0); cp_async_commit();
    load_stage(1, 1); cp_async_commit();

    const uint32_t a_off = ((wm * 64 + lr + lb8 * 8) * SROWB + lb16 * 8) * 2;
    const uint32_t b_off = 2 * WA_PL + ((wn * 64 + lr + lb16 * 8) * SROWB + lb8 * 8) * 2;

    for (int s = 0; s < NS; s++) {
        const int buf = s & 1;
        cp_async_wait<1>();
        __syncthreads();

        const uint32_t base = smem_u32 + buf * WSTAGE_B;

#pragma unroll
        for (int ks = 0; ks < 32; ks += 16) {
            uint32_t bhi[4][4], blo[4][4];
#pragma unroll
            for (int np = 0; np < 4; np++) {
                uint32_t addr = base + b_off + (np * 16 * SROWB + ks) * 2;
                ldsm_x4(bhi[np], addr);
                ldsm_x4(blo[np], addr + WB_PL);
            }
#pragma unroll
            for (int m = 0; m < 4; m++) {
                uint32_t ahi[4], alo[4];
                uint32_t addr = base + a_off + (m * 16 * SROWB + ks) * 2;
                ldsm_x4(ahi, addr);
                ldsm_x4(alo, addr + WA_PL);
#pragma unroll
                for (int n = 0; n < 8; n++) {
                    const uint32_t* bh = &bhi[n >> 1][(n & 1) * 2];
                    const uint32_t* bl = &blo[n >> 1][(n & 1) * 2];
                    mma_bf16(acc[m][n], ahi, bh);
                    mma_bf16(acc[m][n], ahi, bl);
                    mma_bf16(acc[m][n], alo, bh);
                }
            }
        }

        __syncthreads();
        if (s + 2 < NS) load_stage(s + 2, buf);
        cp_async_commit();
    }

    const int g = lane >> 2;
    const int tig = lane & 3;

    if (C) {
#pragma unroll
        for (int m = 0; m < 4; m++) {
            int r0 = m0 + wm * 64 + m * 16 + g;
            int r1 = r0 + 8;
#pragma unroll
            for (int n = 0; n < 8; n++) {
                int col = n0 + wn * 64 + n * 8 + tig * 2;
                *(float2*)(C + (size_t)r0 * N + col) = make_float2(acc[m][n][0], acc[m][n][1]);
                *(float2*)(C + (size_t)r1 * N + col) = make_float2(acc[m][n][2], acc[m][n][3]);
            }
        }
    } else if (n0 < D_MODEL + KV_D) {
        // Q or K region: rope + split via smem staging (fp32, stride 260)
        __nv_bfloat16* dhi = (n0 < D_MODEL) ? Qhi : Khi;
        __nv_bfloat16* dlo = (n0 < D_MODEL) ? Qlo : Klo;
        const int ld = (n0 < D_MODEL) ? D_MODEL : KV_D;
        const int colbase = (n0 < D_MODEL) ? n0 : (n0 - D_MODEL);
        const float scale = (n0 < D_MODEL) ? SOFTMAX_SCALE : 1.0f;

        float* st = (float*)sm;
        __syncthreads();
#pragma unroll
        for (int m = 0; m < 4; m++) {
            int rl = wm * 64 + m * 16 + g;
#pragma unroll
            for (int n = 0; n < 8; n++) {
                int col = wn * 64 + n * 8 + tig * 2;
                *(float2*)&st[rl * 260 + col] = make_float2(acc[m][n][0], acc[m][n][1]);
                *(float2*)&st[(rl + 8) * 260 + col] = make_float2(acc[m][n][2], acc[m][n][3]);
            }
        }
        __syncthreads();
#pragma unroll 4
        for (int p = 0; p < 64; p++) {
            int idx = tid + p * 256;
            int row = idx >> 7;
            int rem = idx & 127;
            int hc = rem >> 6;
            int d = rem & 63;
            float a = st[row * 260 + hc * 128 + d];
            float b = st[row * 260 + hc * 128 + d + 64];
            int sg = m0 + row;
            size_t obase = (size_t)sg * ld + colbase + hc * 128 + d;
            rope_pair_store(a, b, sg, d, scale, cosp, sinp, dhi, dlo, obase);
        }
    } else {
        // V region: plain split
#pragma unroll
        for (int m = 0; m < 4; m++) {
            int r0 = m0 + wm * 64 + m * 16 + g;
            int r1 = r0 + 8;
#pragma unroll
            for (int n = 0; n < 8; n++) {
                int col = n0 - (D_MODEL + KV_D) + wn * 64 + n * 8 + tig * 2;
                uint32_t h0, lo0, h1, lo1;
                split_bf16(make_float2(acc[m][n][0], acc[m][n][1]), h0, lo0);
                split_bf16(make_float2(acc[m][n][2], acc[m][n][3]), h1, lo1);
                *(uint32_t*)&Vhi[(size_t)r0 * KV_D + col] = h0;
                *(uint32_t*)&Vlo[(size_t)r0 * KV_D + col] = lo0;
                *(uint32_t*)&Vhi[(size_t)r1 * KV_D + col] = h1;
                *(uint32_t*)&Vlo[(size_t)r1 * KV_D + col] = lo1;
            }
        }
    }
}

// ---------------------------------------------------------------------------
// Flash attention v3: deferred-PV pipeline.
// FIXES vs round 10/11: (1) have_prev cleared after each consumption,
// (2) PV second n-tile uses FULL A fragment (pp_hi[kc]) with B advanced
//     (vh+2 / vl+2) — round 10 wrongly passed pp_hi[kc]+2 as A (OOB regs).
// ---------------------------------------------------------------------------
#define QROW 136
#define FOFF_QLO 34816
#define FK0 69632                 // K stages: 2 x 34816 (hi@0, lo@17408)
#define FV0 (FK0 + 2 * 34816)     // V stages: 2 x 34816
#define FB_SMEM (FV0 + 2 * 34816) // 208896

__global__ __launch_bounds__(256, 1) void flash_attn_mma3(
        const __nv_bfloat16* __restrict__ Qhi, const __nv_bfloat16* __restrict__ Qlo,
        const __nv_bfloat16* __restrict__ Khi, const __nv_bfloat16* __restrict__ Klo,
        const __nv_bfloat16* __restrict__ Vhi, const __nv_bfloat16* __restrict__ Vlo,
        __nv_bfloat16* __restrict__ Ohi, __nv_bfloat16* __restrict__ Olo) {
    extern __shared__ char sm[];
    const uint32_t smem_u32 = smem_to_u32(sm);

    const int b = blockIdx.x;
    const int qt = (int)(gridDim.x >> 4) - 1 - (b >> 4);
    const int h = b & 15;
    const int kvg = h >> 2;
    const int tid = threadIdx.x;
    const int w = tid >> 5;
    const int lane = tid & 31;
    const int lr = lane & 7;
    const int lb8 = (lane >> 3) & 1;
    const int lb16 = (lane >> 4) & 1;
    const int lg = lane >> 2;
    const int tig = lane & 3;
    const int q0 = qt * 128;
    const int qb = w * 16;

    auto load_k = [&](int jt, int buf) {
        const size_t rowbase = (size_t)(jt * 64) * KV_D + kvg * HD;
#pragma unroll
        for (int i = 0; i < 8; i++) {
            int c = tid + i * 256;
            int plane = c >> 10;
            int idx = c & 1023;
            int row = idx >> 4;
            int ch = idx & 15;
            const __nv_bfloat16* src = (plane ? Klo : Khi) + rowbase + (size_t)row * KV_D + ch * 8;
            cp_async16(smem_u32 + FK0 + buf * 34816 + plane * 17408 +
                       (row * QROW + ch * 8) * 2, src);
        }
    };
    auto load_v = [&](int jt, int buf) {
        const size_t rowbase = (size_t)(jt * 64) * KV_D + kvg * HD;
#pragma unroll
        for (int i = 0; i < 8; i++) {
            int c = tid + i * 256;
            int plane = c >> 10;
            int idx = c & 1023;
            int row = idx >> 4;
            int ch = idx & 15;
            const __nv_bfloat16* src = (plane ? Vlo : Vhi) + rowbase + (size_t)row * KV_D + ch * 8;
            cp_async16(smem_u32 + FV0 + buf * 34816 + plane * 17408 +
                       (row * QROW + ch * 8) * 2, src);
        }
    };

    // Prologue: Q + K(0) in group 0; K(1) + V(0) in group 1
#pragma unroll
    for (int i = 0; i < 16; i++) {
        int c = tid + i * 256;
        int plane = c >> 11;
        int idx = c & 2047;
        int row = idx >> 4;
        int ch = idx & 15;
        const __nv_bfloat16* src = (plane ? Qlo : Qhi) +
            (size_t)(q0 + row) * D_MODEL + h * HD + ch * 8;
        cp_async16(smem_u32 + plane * FOFF_QLO + (row * QROW + ch * 8) * 2, src);
    }
    load_k(0, 0);
    cp_async_commit();
    const int njt = 2 * qt + 2;
    load_k(1, 1);
    load_v(0, 0);
    cp_async_commit();

    const uint32_t qa_hi = smem_u32 + ((qb + lb8 * 8 + lr) * QROW + lb16 * 8) * 2;
    const uint32_t qa_lo = qa_hi + FOFF_QLO;
    const uint32_t k_off = ((lb16 * 8 + lr) * QROW + lb8 * 8) * 2;
    const uint32_t v_off = ((lb8 * 8 + lr) * QROW + lb16 * 8) * 2;

    float m0 = -1e30f, m1 = -1e30f, l0 = 0.0f, l1 = 0.0f;
    float oacc[16][4];
#pragma unroll
    for (int nt = 0; nt < 16; nt++)
#pragma unroll
        for (int j = 0; j < 4; j++) oacc[nt][j] = 0.0f;

    uint32_t pp_hi[4][4], pp_lo[4][4];
    float ap0 = 1.0f, ap1 = 1.0f;
    int have_prev = 0;

    for (int jt = 0; jt < njt; jt++) {
        cp_async_wait<1>();
        __syncthreads();

        const uint32_t kb = smem_u32 + FK0 + (jt & 1) * 34816;
        const uint32_t vb_prev = smem_u32 + FV0 + ((jt & 1) ^ 1) * 34816;
        const bool active = (jt * 64 <= q0 + qb + 15);

        float sacc[8][4];
        if (active) {
#pragma unroll
            for (int nt = 0; nt < 8; nt++)
#pragma unroll
                for (int j = 0; j < 4; j++) sacc[nt][j] = 0.0f;

#pragma unroll
            for (int kc = 0; kc < 8; kc++) {
                uint32_t qhi[4], qlo[4];
                ldsm_x4(qhi, qa_hi + kc * 32);
                ldsm_x4(qlo, qa_lo + kc * 32);
#pragma unroll
                for (int ntp = 0; ntp < 4; ntp++) {
                    uint32_t khi[4], klo[4];
                    uint32_t ka = kb + k_off + ntp * (16 * QROW * 2) + kc * 32;
                    ldsm_x4(khi, ka);
                    ldsm_x4(klo, ka + 17408);
                    mma_bf16(sacc[2 * ntp], qhi, khi);
                    mma_bf16(sacc[2 * ntp], qhi, klo);
                    mma_bf16(sacc[2 * ntp], qlo, khi);
                    mma_bf16(sacc[2 * ntp + 1], qhi, khi + 2);
                    mma_bf16(sacc[2 * ntp + 1], qhi, klo + 2);
                    mma_bf16(sacc[2 * ntp + 1], qlo, khi + 2);
                }
            }
        }

        // Deferred PV of previous tile; consumes pp exactly once.
        // A fragment (P 16x16) is the SAME for both 8-col halves; B advances.
        if (have_prev) {
#pragma unroll
            for (int nt = 0; nt < 16; nt++) {
                oacc[nt][0] *= ap0;
                oacc[nt][1] *= ap0;
                oacc[nt][2] *= ap1;
                oacc[nt][3] *= ap1;
            }
#pragma unroll
            for (int kc = 0; kc < 4; kc++) {
#pragma unroll
                for (int ntp = 0; ntp < 8; ntp++) {
                    uint32_t vh[4], vl[4];
                    uint32_t va = vb_prev + v_off + kc * (16 * QROW * 2) + ntp * 32;
                    ldsm_x4t(vh, va);
                    ldsm_x4t(vl, va + 17408);
                    mma_bf16(oacc[2 * ntp], pp_hi[kc], vh);
                    mma_bf16(oacc[2 * ntp], pp_lo[kc], vh);
                    mma_bf16(oacc[2 * ntp], pp_hi[kc], vl);
                    mma_bf16(oacc[2 * ntp + 1], pp_hi[kc], vh + 2);
                    mma_bf16(oacc[2 * ntp + 1], pp_lo[kc], vh + 2);
                    mma_bf16(oacc[2 * ntp + 1], pp_hi[kc], vl + 2);
                }
            }
            have_prev = 0;
        }

        if (active) {
            if (jt * 64 + 63 > q0 + qb) {
#pragma unroll
                for (int nt = 0; nt < 8; nt++)
#pragma unroll
                    for (int j = 0; j < 4; j++) {
                        int gj = jt * 64 + nt * 8 + tig * 2 + (j & 1);
                        int gi = q0 + qb + lg + ((j >> 1) << 3);
                        if (gj > gi) sacc[nt][j] = -1e30f;
                    }
            }

            float cur0 = -1e30f, cur1 = -1e30f;
#pragma unroll
            for (int nt = 0; nt < 8; nt++) {
                cur0 = fmaxf(cur0, fmaxf(sacc[nt][0], sacc[nt][1]));
                cur1 = fmaxf(cur1, fmaxf(sacc[nt][2], sacc[nt][3]));
            }
            cur0 = fmaxf(cur0, __shfl_xor_sync(0xffffffffu, cur0, 1));
            cur0 = fmaxf(cur0, __shfl_xor_sync(0xffffffffu, cur0, 2));
            cur1 = fmaxf(cur1, __shfl_xor_sync(0xffffffffu, cur1, 1));
            cur1 = fmaxf(cur1, __shfl_xor_sync(0xffffffffu, cur1, 2));

            float mn0 = fmaxf(m0, cur0), mn1 = fmaxf(m1, cur1);
            ap0 = __expf(m0 - mn0);
            ap1 = __expf(m1 - mn1);
            m0 = mn0; m1 = mn1;

            float rs0 = 0.0f, rs1 = 0.0f;
#pragma unroll
            for (int nt = 0; nt < 8; nt++) {
                sacc[nt][0] = __expf(sacc[nt][0] - mn0);
                sacc[nt][1] = __expf(sacc[nt][1] - mn0);
                sacc[nt][2] = __expf(sacc[nt][2] - mn1);
                sacc[nt][3] = __expf(sacc[nt][3] - mn1);
                rs0 += sacc[nt][0] + sacc[nt][1];
                rs1 += sacc[nt][2] + sacc[nt][3];
            }
            rs0 += __shfl_xor_sync(0xffffffffu, rs0, 1);
            rs0 += __shfl_xor_sync(0xffffffffu, rs0, 2);
            rs1 += __shfl_xor_sync(0xffffffffu, rs1, 1);
            rs1 += __shfl_xor_sync(0xffffffffu, rs1, 2);
            l0 = l0 * ap0 + rs0;
            l1 = l1 * ap1 + rs1;

            // pack P for next-iteration PV
#pragma unroll
            for (int kc = 0; kc < 4; kc++) {
                split_bf16(make_float2(sacc[2 * kc][0], sacc[2 * kc][1]), pp_hi[kc][0], pp_lo[kc][0]);
                split_bf16(make_float2(sacc[2 * kc][2], sacc[2 * kc][3]), pp_hi[kc][1], pp_lo[kc][1]);
                split_bf16(make_float2(sacc[2 * kc + 1][0], sacc[2 * kc + 1][1]), pp_hi[kc][2], pp_lo[kc][2]);
                split_bf16(make_float2(sacc[2 * kc + 1][2], sacc[2 * kc + 1][3]), pp_hi[kc][3], pp_lo[kc][3]);
            }
            have_prev = 1;
        }

        __syncthreads();
        if (jt + 2 < njt) load_k(jt + 2, jt & 1);
        if (jt + 1 < njt) load_v(jt + 1, (jt + 1) & 1);
        cp_async_commit();
    }

    // Final deferred PV: warps whose last P is unconsumed (active at njt-1).
    cp_async_wait<0>();
    __syncthreads();
    if (have_prev) {
        const uint32_t vb_last = smem_u32 + FV0 + ((njt - 1) & 1) * 34816;
#pragma unroll
        for (int nt = 0; nt < 16; nt++) {
            oacc[nt][0] *= ap0;
            oacc[nt][1] *= ap0;
            oacc[nt][2] *= ap1;
            oacc[nt][3] *= ap1;
        }
#pragma unroll
        for (int kc = 0; kc < 4; kc++) {
#pragma unroll
            for (int ntp = 0; ntp < 8; ntp++) {
                uint32_t vh[4], vl[4];
                uint32_t va = vb_last + v_off + kc * (16 * QROW * 2) + ntp * 32;
                ldsm_x4t(vh, va);
                ldsm_x4t(vl, va + 17408);
                mma_bf16(oacc[2 * ntp], pp_hi[kc], vh);
                mma_bf16(oacc[2 * ntp], pp_lo[kc], vh);
                mma_bf16(oacc[2 * ntp], pp_hi[kc], vl);
                mma_bf16(oacc[2 * ntp + 1], pp_hi[kc], vh + 2);
                mma_bf16(oacc[2 * ntp + 1], pp_lo[kc], vh + 2);
                mma_bf16(oacc[2 * ntp + 1], pp_hi[kc], vl + 2);
            }
        }
    }

    float inv0 = 1.0f / l0;
    float inv1 = 1.0f / l1;
    int row0 = q0 + qb + lg;
    int row1 = row0 + 8;
#pragma unroll
    for (int nt = 0; nt < 16; nt++) {
        int col = h * HD + nt * 8 + tig * 2;
        uint32_t h0, lo0, h1, lo1;
        split_bf16(make_float2(oacc[nt][0] * inv0, oacc[nt][1] * inv0), h0, lo0);
        split_bf16(make_float2(oacc[nt][2] * inv1, oacc[nt][3] * inv1), h1, lo1);
        *(uint32_t*)&Ohi[(size_t)row0 * D_MODEL + col] = h0;
        *(uint32_t*)&Olo[(size_t)row0 * D_MODEL + col] = lo0;
        *(uint32_t*)&Ohi[(size_t)row1 * D_MODEL + col] = h1;
        *(uint32_t*)&Olo[(size_t)row1 * D_MODEL + col] = lo1;
    }
}

// ---------------------------------------------------------------------------
extern "C" void kernel_launch(void* const* d_in, const int* in_sizes, int n_in,
                              void* d_out, int out_size) {
    const float* x    = (const float*)d_in[0];
    const float* wq   = (const float*)d_in[2];
    const float* wk   = (const float*)d_in[3];
    const float* wv   = (const float*)d_in[4];
    const float* wo   = (const float*)d_in[5];
    const float* cosp = (const float*)d_in[6];
    const float* sinp = (const float*)d_in[7];
    float* out = (float*)d_out;

    __nv_bfloat16 *xhi, *xlo, *qhi, *qlo, *khi, *klo, *vhi, *vlo, *ctxhi, *ctxlo;
    __nv_bfloat16 *wThi, *wTlo, *woThi, *woTlo;
    cudaGetSymbolAddress((void**)&xhi, g_xhi);
    cudaGetSymbolAddress((void**)&xlo, g_xlo);
    cudaGetSymbolAddress((void**)&qhi, g_qhi);
    cudaGetSymbolAddress((void**)&qlo, g_qlo);
    cudaGetSymbolAddress((void**)&khi, g_khi);
    cudaGetSymbolAddress((void**)&klo, g_klo);
    cudaGetSymbolAddress((void**)&vhi, g_vhi);
    cudaGetSymbolAddress((void**)&vlo, g_vlo);
    cudaGetSymbolAddress((void**)&ctxhi, g_ctxhi);
    cudaGetSymbolAddress((void**)&ctxlo, g_ctxlo);
    cudaGetSymbolAddress((void**)&wThi, g_wThi);
    cudaGetSymbolAddress((void**)&wTlo, g_wTlo);
    cudaGetSymbolAddress((void**)&woThi, g_woThi);
    cudaGetSymbolAddress((void**)&woTlo, g_woTlo);

    cudaFuncSetAttribute(gemm_bf16p_wide, cudaFuncAttributeMaxDynamicSharedMemorySize, GW_SMEM);
    cudaFuncSetAttribute(flash_attn_mma3, cudaFuncAttributeMaxDynamicSharedMemorySize, FB_SMEM);

    // Pre-split x and weights (wq/wk/wv into one concatenated [3072,2048])
    {
        int n4 = S_LEN * D_MODEL / 4;
        split_kernel<<<(n4 + 255) / 256, 256>>>(x, xhi, xlo, n4);
    }
    transpose_split_kernel<<<dim3(D_MODEL / 32, D_MODEL / 32), dim3(32, 8)>>>(
        wq, wThi, wTlo, D_MODEL, D_MODEL);
    transpose_split_kernel<<<dim3(KV_D / 32, D_MODEL / 32), dim3(32, 8)>>>(
        wk, wThi + (size_t)D_MODEL * D_MODEL, wTlo + (size_t)D_MODEL * D_MODEL, D_MODEL, KV_D);
    transpose_split_kernel<<<dim3(KV_D / 32, D_MODEL / 32), dim3(32, 8)>>>(
        wv, wThi + (size_t)(D_MODEL + KV_D) * D_MODEL,
        wTlo + (size_t)(D_MODEL + KV_D) * D_MODEL, D_MODEL, KV_D);
    transpose_split_kernel<<<dim3(D_MODEL / 32, D_MODEL / 32), dim3(32, 8)>>>(
        wo, woThi, woTlo, D_MODEL, D_MODEL);

    // Merged QKV projection (one launch; per-region rope/split epilogues)
    gemm_bf16p_wide<<<dim3(QKV_N / 256, S_LEN / 128), 256, GW_SMEM>>>(
        xhi, xlo, wThi, wTlo, nullptr,
        qhi, qlo, khi, klo, vhi, vlo, cosp, sinp,
        S_LEN, QKV_N, D_MODEL);

    // Flash attention (deferred-PV pipeline; writes ctx hi/lo planes)
    flash_attn_mma3<<<dim3((S_LEN / 128) * NH, 1), 256, FB_SMEM>>>(
        qhi, qlo, khi, klo, vhi, vlo, ctxhi, ctxlo);

    // Output projection (fp32 out)
    gemm_bf16p_wide<<<dim3(D_MODEL / 256, S_LEN / 128), 256, GW_SMEM>>>(
        ctxhi, ctxlo, woThi, woTlo, out,
        nullptr, nullptr, nullptr, nullptr, nullptr, nullptr, nullptr, nullptr,
        S_LEN, D_MODEL, D_MODEL);
}

// round 13
// speedup vs baseline: 1.0298x; 1.0298x over previous
#include <cuda_runtime.h>
#include <cuda_bf16.h>
#include <cstdint>

// Problem constants
#define S_LEN 4096
#define D_MODEL 2048
#define NH 16
#define NG 4
#define HD 128
#define KV_D (NG * HD)          // 512
#define QKV_N (D_MODEL + 2 * KV_D)  // 3072
#define SOFTMAX_SCALE 0.08838834764831845f  // 1/sqrt(128)

// bf16 hi/lo planes
__device__ __nv_bfloat16 g_xhi[S_LEN * D_MODEL];
__device__ __nv_bfloat16 g_xlo[S_LEN * D_MODEL];
__device__ __nv_bfloat16 g_qhi[S_LEN * D_MODEL];
__device__ __nv_bfloat16 g_qlo[S_LEN * D_MODEL];
__device__ __nv_bfloat16 g_khi[S_LEN * KV_D];
__device__ __nv_bfloat16 g_klo[S_LEN * KV_D];
__device__ __nv_bfloat16 g_vhi[S_LEN * KV_D];
__device__ __nv_bfloat16 g_vlo[S_LEN * KV_D];
__device__ __nv_bfloat16 g_ctxhi[S_LEN * D_MODEL];
__device__ __nv_bfloat16 g_ctxlo[S_LEN * D_MODEL];
__device__ __nv_bfloat16 g_wThi[QKV_N * D_MODEL];   // rows: 0-2047 Q, 2048-2559 K, 2560-3071 V
__device__ __nv_bfloat16 g_wTlo[QKV_N * D_MODEL];
__device__ __nv_bfloat16 g_woThi[D_MODEL * D_MODEL];
__device__ __nv_bfloat16 g_woTlo[D_MODEL * D_MODEL];

// ---------------------------------------------------------------------------
// Helpers
// ---------------------------------------------------------------------------
__device__ __forceinline__ uint32_t smem_to_u32(const void* p) {
    uint32_t a;
    asm("{ .reg .u64 t; cvta.to.shared.u64 t, %1; cvt.u32.u64 %0, t; }"
        : "=r"(a) : "l"(p));
    return a;
}

__device__ __forceinline__ void cp_async16(uint32_t smem_addr, const void* gptr) {
    asm volatile("cp.async.cg.shared.global [%0], [%1], 16;" :: "r"(smem_addr), "l"(gptr));
}
__device__ __forceinline__ void cp_async_commit() {
    asm volatile("cp.async.commit_group;" ::: "memory");
}
template <int N>
__device__ __forceinline__ void cp_async_wait() {
    asm volatile("cp.async.wait_group %0;" :: "n"(N) : "memory");
}

__device__ __forceinline__ uint32_t pack_bf16(float x, float y) {
    uint32_t r;
    asm("cvt.rn.bf16x2.f32 %0, %1, %2;" : "=r"(r) : "f"(y), "f"(x));
    return r;
}
__device__ __forceinline__ float bf16lo_f32(uint32_t h) { return __uint_as_float(h << 16); }
__device__ __forceinline__ float bf16hi_f32(uint32_t h) { return __uint_as_float(h & 0xffff0000u); }

__device__ __forceinline__ void split_bf16(float2 f, uint32_t& hi, uint32_t& lo) {
    hi = pack_bf16(f.x, f.y);
    float rx = f.x - bf16lo_f32(hi);
    float ry = f.y - bf16hi_f32(hi);
    lo = pack_bf16(rx, ry);
}

__device__ __forceinline__ void mma_bf16(float* c, const uint32_t* a, const uint32_t* b) {
    asm volatile(
        "mma.sync.aligned.m16n8k16.row.col.f32.bf16.bf16.f32 "
        "{%0,%1,%2,%3}, {%4,%5,%6,%7}, {%8,%9}, {%0,%1,%2,%3};"
        : "+f"(c[0]), "+f"(c[1]), "+f"(c[2]), "+f"(c[3])
        : "r"(a[0]), "r"(a[1]), "r"(a[2]), "r"(a[3]), "r"(b[0]), "r"(b[1]));
}

__device__ __forceinline__ void ldsm_x4(uint32_t* r, uint32_t addr) {
    asm volatile("ldmatrix.sync.aligned.m8n8.x4.shared.b16 {%0,%1,%2,%3}, [%4];"
        : "=r"(r[0]), "=r"(r[1]), "=r"(r[2]), "=r"(r[3]) : "r"(addr));
}
__device__ __forceinline__ void ldsm_x4t(uint32_t* r, uint32_t addr) {
    asm volatile("ldmatrix.sync.aligned.m8n8.x4.trans.shared.b16 {%0,%1,%2,%3}, [%4];"
        : "=r"(r[0]), "=r"(r[1]), "=r"(r[2]), "=r"(r[3]) : "r"(addr));
}

// rope one pair in fp32 then split to bf16 planes
__device__ __forceinline__ void rope_pair_store(
        float a, float b, int sg, int d, float scale,
        const float* __restrict__ cosp, const float* __restrict__ sinp,
        __nv_bfloat16* __restrict__ hi, __nv_bfloat16* __restrict__ lo, size_t obase) {
    float c1 = cosp[sg * 128 + d],      s1 = sinp[sg * 128 + d];
    float c2 = cosp[sg * 128 + d + 64], s2 = sinp[sg * 128 + d + 64];
    float o1 = (a * c1 - b * s1) * scale;
    float o2 = (b * c2 + a * s2) * scale;
    __nv_bfloat16 h1 = __float2bfloat16(o1);
    __nv_bfloat16 L1 = __float2bfloat16(o1 - __bfloat162float(h1));
    __nv_bfloat16 h2 = __float2bfloat16(o2);
    __nv_bfloat16 L2 = __float2bfloat16(o2 - __bfloat162float(h2));
    hi[obase] = h1;      lo[obase] = L1;
    hi[obase + 64] = h2; lo[obase + 64] = L2;
}

// ---------------------------------------------------------------------------
// Split kernels
// ---------------------------------------------------------------------------
__global__ void split_kernel(const float* __restrict__ in,
                             __nv_bfloat16* __restrict__ hi,
                             __nv_bfloat16* __restrict__ lo,
                             int n4) {
    int idx = blockIdx.x * blockDim.x + threadIdx.x;
    if (idx >= n4) return;
    float4 v = ((const float4*)in)[idx];
    uint32_t h01, l01, h23, l23;
    split_bf16(make_float2(v.x, v.y), h01, l01);
    split_bf16(make_float2(v.z, v.w), h23, l23);
    ((uint2*)hi)[idx] = make_uint2(h01, h23);
    ((uint2*)lo)[idx] = make_uint2(l01, l23);
}

__global__ void transpose_split_kernel(const float* __restrict__ in,
                                       __nv_bfloat16* __restrict__ hiT,
                                       __nv_bfloat16* __restrict__ loT,
                                       int R, int C) {
    __shared__ float t[32][33];
    int c0 = blockIdx.x * 32, r0 = blockIdx.y * 32;
    int x = threadIdx.x, y = threadIdx.y;
#pragma unroll
    for (int i = y; i < 32; i += 8) t[i][x] = in[(size_t)(r0 + i) * C + c0 + x];
    __syncthreads();
#pragma unroll
    for (int i = y; i < 32; i += 8) {
        float v = t[x][i];
        __nv_bfloat16 h = __float2bfloat16(v);
        __nv_bfloat16 l = __float2bfloat16(v - __bfloat162float(h));
        size_t o = (size_t)(c0 + i) * R + r0 + x;
        hiT[o] = h;
        loT[o] = l;
    }
}

// ---------------------------------------------------------------------------
// GEMM 128x128, BK=32, 2-stage, SROW2=40 (conflict-free ldsm), 2 CTAs/SM.
// Modes:
//   C != null : plain fp32 store (O projection)
//   C == null : region epilogue by n0:
//       n0 < 2048          -> rope+scale+split to Q planes (ld 2048)
//       2048 <= n0 < 2560  -> rope+split to K planes (ld 512)
//       n0 >= 2560         -> plain split to V planes (ld 512)
// ---------------------------------------------------------------------------
#define SROW2 40
#define PL2 (128 * SROW2 * 2)        // 10240 B per plane
#define STG2 (4 * PL2)               // 40960 B per stage
#define GM2_SMEM (2 * STG2)          // 81920 B -> 2 CTAs/SM

__global__ __launch_bounds__(256, 2) void gemm_bf16p_128(
        const __nv_bfloat16* __restrict__ Ahi, const __nv_bfloat16* __restrict__ Alo,
        const __nv_bfloat16* __restrict__ Bhi, const __nv_bfloat16* __restrict__ Blo,
        float* __restrict__ C,
        __nv_bfloat16* __restrict__ Qhi, __nv_bfloat16* __restrict__ Qlo,
        __nv_bfloat16* __restrict__ Khi, __nv_bfloat16* __restrict__ Klo,
        __nv_bfloat16* __restrict__ Vhi, __nv_bfloat16* __restrict__ Vlo,
        const float* __restrict__ cosp, const float* __restrict__ sinp,
        int M, int N, int K) {
    extern __shared__ char sm[];
    const uint32_t smem_u32 = smem_to_u32(sm);

    const int tid = threadIdx.x;
    const int wid = tid >> 5;
    const int lane = tid & 31;
    const int lr = lane & 7;
    const int lb8 = (lane >> 3) & 1;
    const int lb16 = (lane >> 4) & 1;
    const int wm = wid >> 2;
    const int wn = wid & 3;
    const int m0 = blockIdx.y * 128;
    const int n0 = blockIdx.x * 128;
    const int NS = K >> 5;

    const __nv_bfloat16* srcs[4] = {Ahi, Alo, Bhi, Blo};

    auto load_stage = [&](int s, int buf) {
        const int k0 = s << 5;
        const uint32_t base = smem_u32 + buf * STG2;
#pragma unroll
        for (int i = 0; i < 8; i++) {
            int c = tid + i * 256;
            int plane = c >> 9;
            int idx = c & 511;
            int row = idx >> 2;
            int ch = idx & 3;
            int grow = (plane < 2 ? m0 : n0) + row;
            const __nv_bfloat16* g = srcs[plane] + (size_t)grow * K + k0 + ch * 8;
            cp_async16(base + plane * PL2 + (row * SROW2 + ch * 8) * 2, g);
        }
    };

    float acc[4][4][4];
#pragma unroll
    for (int m = 0; m < 4; m++)
#pragma unroll
        for (int n = 0; n < 4; n++)
#pragma unroll
            for (int i = 0; i < 4; i++) acc[m][n][i] = 0.0f;

    load_stage(0, 0); cp_async_commit();
    load_stage(1, 1); cp_async_commit();

    const uint32_t a_off = ((wm * 64 + lr + lb8 * 8) * SROW2 + lb16 * 8) * 2;
    const uint32_t b_off = 2 * PL2 + ((wn * 32 + lr + lb16 * 8) * SROW2 + lb8 * 8) * 2;

    for (int s = 0; s < NS; s++) {
        const int buf = s & 1;
        cp_async_wait<1>();
        __syncthreads();

        const uint32_t base = smem_u32 + buf * STG2;

#pragma unroll
        for (int ks = 0; ks < 32; ks += 16) {
            uint32_t bhi[2][4], blo[2][4];
#pragma unroll
            for (int np = 0; np < 2; np++) {
                uint32_t addr = base + b_off + (np * 16 * SROW2 + ks) * 2;
                ldsm_x4(bhi[np], addr);
                ldsm_x4(blo[np], addr + PL2);
            }
#pragma unroll
            for (int m = 0; m < 4; m++) {
                uint32_t ahi[4], alo[4];
                uint32_t addr = base + a_off + (m * 16 * SROW2 + ks) * 2;
                ldsm_x4(ahi, addr);
                ldsm_x4(alo, addr + PL2);
#pragma unroll
                for (int n = 0; n < 4; n++) {
                    const uint32_t* bh = &bhi[n >> 1][(n & 1) * 2];
                    const uint32_t* bl = &blo[n >> 1][(n & 1) * 2];
                    mma_bf16(acc[m][n], ahi, bh);
                    mma_bf16(acc[m][n], ahi, bl);
                    mma_bf16(acc[m][n], alo, bh);
                }
            }
        }

        __syncthreads();
        if (s + 2 < NS) load_stage(s + 2, buf);
        cp_async_commit();
    }

    const int g = lane >> 2;
    const int tig = lane & 3;

    if (C) {
#pragma unroll
        for (int m = 0; m < 4; m++) {
            int r0 = m0 + wm * 64 + m * 16 + g;
            int r1 = r0 + 8;
#pragma unroll
            for (int n = 0; n < 4; n++) {
                int col = n0 + wn * 32 + n * 8 + tig * 2;
                *(float2*)(C + (size_t)r0 * N + col) = make_float2(acc[m][n][0], acc[m][n][1]);
                *(float2*)(C + (size_t)r1 * N + col) = make_float2(acc[m][n][2], acc[m][n][3]);
            }
        }
    } else if (n0 < D_MODEL + KV_D) {
        // Q or K region: rope + split via smem staging (fp32, stride 132).
        // 128-col tile == exactly one head, so pairs (d, d+64) are in-tile.
        __nv_bfloat16* dhi = (n0 < D_MODEL) ? Qhi : Khi;
        __nv_bfloat16* dlo = (n0 < D_MODEL) ? Qlo : Klo;
        const int ld = (n0 < D_MODEL) ? D_MODEL : KV_D;
        const int colbase = (n0 < D_MODEL) ? n0 : (n0 - D_MODEL);
        const float scale = (n0 < D_MODEL) ? SOFTMAX_SCALE : 1.0f;

        float* st = (float*)sm;
        __syncthreads();
#pragma unroll
        for (int m = 0; m < 4; m++) {
            int rl = wm * 64 + m * 16 + g;
#pragma unroll
            for (int n = 0; n < 4; n++) {
                int col = wn * 32 + n * 8 + tig * 2;
                *(float2*)&st[rl * 132 + col] = make_float2(acc[m][n][0], acc[m][n][1]);
                *(float2*)&st[(rl + 8) * 132 + col] = make_float2(acc[m][n][2], acc[m][n][3]);
            }
        }
        __syncthreads();
#pragma unroll 4
        for (int p = 0; p < 32; p++) {
            int idx = tid + p * 256;
            int row = idx >> 6;
            int d = idx & 63;
            float a = st[row * 132 + d];
            float b = st[row * 132 + d + 64];
            int sg = m0 + row;
            size_t obase = (size_t)sg * ld + colbase + d;
            rope_pair_store(a, b, sg, d, scale, cosp, sinp, dhi, dlo, obase);
        }
    } else {
        // V region: plain split
#pragma unroll
        for (int m = 0; m < 4; m++) {
            int r0 = m0 + wm * 64 + m * 16 + g;
            int r1 = r0 + 8;
#pragma unroll
            for (int n = 0; n < 4; n++) {
                int col = n0 - (D_MODEL + KV_D) + wn * 32 + n * 8 + tig * 2;
                uint32_t h0, lo0, h1, lo1;
                split_bf16(make_float2(acc[m][n][0], acc[m][n][1]), h0, lo0);
                split_bf16(make_float2(acc[m][n][2], acc[m][n][3]), h1, lo1);
                *(uint32_t*)&Vhi[(size_t)r0 * KV_D + col] = h0;
                *(uint32_t*)&Vlo[(size_t)r0 * KV_D + col] = lo0;
                *(uint32_t*)&Vhi[(size_t)r1 * KV_D + col] = h1;
                *(uint32_t*)&Vlo[(size_t)r1 * KV_D + col] = lo1;
            }
        }
    }
}

// ---------------------------------------------------------------------------
// Flash attention v3 (round-12, passing): deferred-PV pipeline.
// ---------------------------------------------------------------------------
#define QROW 136
#define FOFF_QLO 34816
#define FK0 69632                 // K stages: 2 x 34816 (hi@0, lo@17408)
#define FV0 (FK0 + 2 * 34816)     // V stages: 2 x 34816
#define FB_SMEM (FV0 + 2 * 34816) // 208896

__global__ __launch_bounds__(256, 1) void flash_attn_mma3(
        const __nv_bfloat16* __restrict__ Qhi, const __nv_bfloat16* __restrict__ Qlo,
        const __nv_bfloat16* __restrict__ Khi, const __nv_bfloat16* __restrict__ Klo,
        const __nv_bfloat16* __restrict__ Vhi, const __nv_bfloat16* __restrict__ Vlo,
        __nv_bfloat16* __restrict__ Ohi, __nv_bfloat16* __restrict__ Olo) {
    extern __shared__ char sm[];
    const uint32_t smem_u32 = smem_to_u32(sm);

    const int b = blockIdx.x;
    const int qt = (int)(gridDim.x >> 4) - 1 - (b >> 4);
    const int h = b & 15;
    const int kvg = h >> 2;
    const int tid = threadIdx.x;
    const int w = tid >> 5;
    const int lane = tid & 31;
    const int lr = lane & 7;
    const int lb8 = (lane >> 3) & 1;
    const int lb16 = (lane >> 4) & 1;
    const int lg = lane >> 2;
    const int tig = lane & 3;
    const int q0 = qt * 128;
    const int qb = w * 16;

    auto load_k = [&](int jt, int buf) {
        const size_t rowbase = (size_t)(jt * 64) * KV_D + kvg * HD;
#pragma unroll
        for (int i = 0; i < 8; i++) {
            int c = tid + i * 256;
            int plane = c >> 10;
            int idx = c & 1023;
            int row = idx >> 4;
            int ch = idx & 15;
            const __nv_bfloat16* src = (plane ? Klo : Khi) + rowbase + (size_t)row * KV_D + ch * 8;
            cp_async16(smem_u32 + FK0 + buf * 34816 + plane * 17408 +
                       (row * QROW + ch * 8) * 2, src);
        }
    };
    auto load_v = [&](int jt, int buf) {
        const size_t rowbase = (size_t)(jt * 64) * KV_D + kvg * HD;
#pragma unroll
        for (int i = 0; i < 8; i++) {
            int c = tid + i * 256;
            int plane = c >> 10;
            int idx = c & 1023;
            int row = idx >> 4;
            int ch = idx & 15;
            const __nv_bfloat16* src = (plane ? Vlo : Vhi) + rowbase + (size_t)row * KV_D + ch * 8;
            cp_async16(smem_u32 + FV0 + buf * 34816 + plane * 17408 +
                       (row * QROW + ch * 8) * 2, src);
        }
    };

    // Prologue
#pragma unroll
    for (int i = 0; i < 16; i++) {
        int c = tid + i * 256;
        int plane = c >> 11;
        int idx = c & 2047;
        int row = idx >> 4;
        int ch = idx & 15;
        const __nv_bfloat16* src = (plane ? Qlo : Qhi) +
            (size_t)(q0 + row) * D_MODEL + h * HD + ch * 8;
        cp_async16(smem_u32 + plane * FOFF_QLO + (row * QROW + ch * 8) * 2, src);
    }
    load_k(0, 0);
    cp_async_commit();
    const int njt = 2 * qt + 2;
    load_k(1, 1);
    load_v(0, 0);
    cp_async_commit();

    const uint32_t qa_hi = smem_u32 + ((qb + lb8 * 8 + lr) * QROW + lb16 * 8) * 2;
    const uint32_t qa_lo = qa_hi + FOFF_QLO;
    const uint32_t k_off = ((lb16 * 8 + lr) * QROW + lb8 * 8) * 2;
    const uint32_t v_off = ((lb8 * 8 + lr) * QROW + lb16 * 8) * 2;

    float m0 = -1e30f, m1 = -1e30f, l0 = 0.0f, l1 = 0.0f;
    float oacc[16][4];
#pragma unroll
    for (int nt = 0; nt < 16; nt++)
#pragma unroll
        for (int j = 0; j < 4; j++) oacc[nt][j] = 0.0f;

    uint32_t pp_hi[4][4], pp_lo[4][4];
    float ap0 = 1.0f, ap1 = 1.0f;
    int have_prev = 0;

    for (int jt = 0; jt < njt; jt++) {
        cp_async_wait<1>();
        __syncthreads();

        const uint32_t kb = smem_u32 + FK0 + (jt & 1) * 34816;
        const uint32_t vb_prev = smem_u32 + FV0 + ((jt & 1) ^ 1) * 34816;
        const bool active = (jt * 64 <= q0 + qb + 15);

        float sacc[8][4];
        if (active) {
#pragma unroll
            for (int nt = 0; nt < 8; nt++)
#pragma unroll
                for (int j = 0; j < 4; j++) sacc[nt][j] = 0.0f;

#pragma unroll
            for (int kc = 0; kc < 8; kc++) {
                uint32_t qhi[4], qlo[4];
                ldsm_x4(qhi, qa_hi + kc * 32);
                ldsm_x4(qlo, qa_lo + kc * 32);
#pragma unroll
                for (int ntp = 0; ntp < 4; ntp++) {
                    uint32_t khi[4], klo[4];
                    uint32_t ka = kb + k_off + ntp * (16 * QROW * 2) + kc * 32;
                    ldsm_x4(khi, ka);
                    ldsm_x4(klo, ka + 17408);
                    mma_bf16(sacc[2 * ntp], qhi, khi);
                    mma_bf16(sacc[2 * ntp], qhi, klo);
                    mma_bf16(sacc[2 * ntp], qlo, khi);
                    mma_bf16(sacc[2 * ntp + 1], qhi, khi + 2);
                    mma_bf16(sacc[2 * ntp + 1], qhi, klo + 2);
                    mma_bf16(sacc[2 * ntp + 1], qlo, khi + 2);
                }
            }
        }

        if (have_prev) {
#pragma unroll
            for (int nt = 0; nt < 16; nt++) {
                oacc[nt][0] *= ap0;
                oacc[nt][1] *= ap0;
                oacc[nt][2] *= ap1;
                oacc[nt][3] *= ap1;
            }
#pragma unroll
            for (int kc = 0; kc < 4; kc++) {
#pragma unroll
                for (int ntp = 0; ntp < 8; ntp++) {
                    uint32_t vh[4], vl[4];
                    uint32_t va = vb_prev + v_off + kc * (16 * QROW * 2) + ntp * 32;
                    ldsm_x4t(vh, va);
                    ldsm_x4t(vl, va + 17408);
                    mma_bf16(oacc[2 * ntp], pp_hi[kc], vh);
                    mma_bf16(oacc[2 * ntp], pp_lo[kc], vh);
                    mma_bf16(oacc[2 * ntp], pp_hi[kc], vl);
                    mma_bf16(oacc[2 * ntp + 1], pp_hi[kc], vh + 2);
                    mma_bf16(oacc[2 * ntp + 1], pp_lo[kc], vh + 2);
                    mma_bf16(oacc[2 * ntp + 1], pp_hi[kc], vl + 2);
                }
            }
            have_prev = 0;
        }

        if (active) {
            if (jt * 64 + 63 > q0 + qb) {
#pragma unroll
                for (int nt = 0; nt < 8; nt++)
#pragma unroll
                    for (int j = 0; j < 4; j++) {
                        int gj = jt * 64 + nt * 8 + tig * 2 + (j & 1);
                        int gi = q0 + qb + lg + ((j >> 1) << 3);
                        if (gj > gi) sacc[nt][j] = -1e30f;
                    }
            }

            float cur0 = -1e30f, cur1 = -1e30f;
#pragma unroll
            for (int nt = 0; nt < 8; nt++) {
                cur0 = fmaxf(cur0, fmaxf(sacc[nt][0], sacc[nt][1]));
                cur1 = fmaxf(cur1, fmaxf(sacc[nt][2], sacc[nt][3]));
            }
            cur0 = fmaxf(cur0, __shfl_xor_sync(0xffffffffu, cur0, 1));
            cur0 = fmaxf(cur0, __shfl_xor_sync(0xffffffffu, cur0, 2));
            cur1 = fmaxf(cur1, __shfl_xor_sync(0xffffffffu, cur1, 1));
            cur1 = fmaxf(cur1, __shfl_xor_sync(0xffffffffu, cur1, 2));

            float mn0 = fmaxf(m0, cur0), mn1 = fmaxf(m1, cur1);
            ap0 = __expf(m0 - mn0);
            ap1 = __expf(m1 - mn1);
            m0 = mn0; m1 = mn1;

            float rs0 = 0.0f, rs1 = 0.0f;
#pragma unroll
            for (int nt = 0; nt < 8; nt++) {
                sacc[nt][0] = __expf(sacc[nt][0] - mn0);
                sacc[nt][1] = __expf(sacc[nt][1] - mn0);
                sacc[nt][2] = __expf(sacc[nt][2] - mn1);
                sacc[nt][3] = __expf(sacc[nt][3] - mn1);
                rs0 += sacc[nt][0] + sacc[nt][1];
                rs1 += sacc[nt][2] + sacc[nt][3];
            }
            rs0 += __shfl_xor_sync(0xffffffffu, rs0, 1);
            rs0 += __shfl_xor_sync(0xffffffffu, rs0, 2);
            rs1 += __shfl_xor_sync(0xffffffffu, rs1, 1);
            rs1 += __shfl_xor_sync(0xffffffffu, rs1, 2);
            l0 = l0 * ap0 + rs0;
            l1 = l1 * ap1 + rs1;

#pragma unroll
            for (int kc = 0; kc < 4; kc++) {
                split_bf16(make_float2(sacc[2 * kc][0], sacc[2 * kc][1]), pp_hi[kc][0], pp_lo[kc][0]);
                split_bf16(make_float2(sacc[2 * kc][2], sacc[2 * kc][3]), pp_hi[kc][1], pp_lo[kc][1]);
                split_bf16(make_float2(sacc[2 * kc + 1][0], sacc[2 * kc + 1][1]), pp_hi[kc][2], pp_lo[kc][2]);
                split_bf16(make_float2(sacc[2 * kc + 1][2], sacc[2 * kc + 1][3]), pp_hi[kc][3], pp_lo[kc][3]);
            }
            have_prev = 1;
        }

        __syncthreads();
        if (jt + 2 < njt) load_k(jt + 2, jt & 1);
        if (jt + 1 < njt) load_v(jt + 1, (jt + 1) & 1);
        cp_async_commit();
    }

    cp_async_wait<0>();
    __syncthreads();
    if (have_prev) {
        const uint32_t vb_last = smem_u32 + FV0 + ((njt - 1) & 1) * 34816;
#pragma unroll
        for (int nt = 0; nt < 16; nt++) {
            oacc[nt][0] *= ap0;
            oacc[nt][1] *= ap0;
            oacc[nt][2] *= ap1;
            oacc[nt][3] *= ap1;
        }
#pragma unroll
        for (int kc = 0; kc < 4; kc++) {
#pragma unroll
            for (int ntp = 0; ntp < 8; ntp++) {
                uint32_t vh[4], vl[4];
                uint32_t va = vb_last + v_off + kc * (16 * QROW * 2) + ntp * 32;
                ldsm_x4t(vh, va);
                ldsm_x4t(vl, va + 17408);
                mma_bf16(oacc[2 * ntp], pp_hi[kc], vh);
                mma_bf16(oacc[2 * ntp], pp_lo[kc], vh);
                mma_bf16(oacc[2 * ntp], pp_hi[kc], vl);
                mma_bf16(oacc[2 * ntp + 1], pp_hi[kc], vh + 2);
                mma_bf16(oacc[2 * ntp + 1], pp_lo[kc], vh + 2);
                mma_bf16(oacc[2 * ntp + 1], pp_hi[kc], vl + 2);
            }
        }
    }

    float inv0 = 1.0f / l0;
    float inv1 = 1.0f / l1;
    int row0 = q0 + qb + lg;
    int row1 = row0 + 8;
#pragma unroll
    for (int nt = 0; nt < 16; nt++) {
        int col = h * HD + nt * 8 + tig * 2;
        uint32_t h0, lo0, h1, lo1;
        split_bf16(make_float2(oacc[nt][0] * inv0, oacc[nt][1] * inv0), h0, lo0);
        split_bf16(make_float2(oacc[nt][2] * inv1, oacc[nt][3] * inv1), h1, lo1);
        *(uint32_t*)&Ohi[(size_t)row0 * D_MODEL + col] = h0;
        *(uint32_t*)&Olo[(size_t)row0 * D_MODEL + col] = lo0;
        *(uint32_t*)&Ohi[(size_t)row1 * D_MODEL + col] = h1;
        *(uint32_t*)&Olo[(size_t)row1 * D_MODEL + col] = lo1;
    }
}

// ---------------------------------------------------------------------------
extern "C" void kernel_launch(void* const* d_in, const int* in_sizes, int n_in,
                              void* d_out, int out_size) {
    const float* x    = (const float*)d_in[0];
    const float* wq   = (const float*)d_in[2];
    const float* wk   = (const float*)d_in[3];
    const float* wv   = (const float*)d_in[4];
    const float* wo   = (const float*)d_in[5];
    const float* cosp = (const float*)d_in[6];
    const float* sinp = (const float*)d_in[7];
    float* out = (float*)d_out;

    __nv_bfloat16 *xhi, *xlo, *qhi, *qlo, *khi, *klo, *vhi, *vlo, *ctxhi, *ctxlo;
    __nv_bfloat16 *wThi, *wTlo, *woThi, *woTlo;
    cudaGetSymbolAddress((void**)&xhi, g_xhi);
    cudaGetSymbolAddress((void**)&xlo, g_xlo);
    cudaGetSymbolAddress((void**)&qhi, g_qhi);
    cudaGetSymbolAddress((void**)&qlo, g_qlo);
    cudaGetSymbolAddress((void**)&khi, g_khi);
    cudaGetSymbolAddress((void**)&klo, g_klo);
    cudaGetSymbolAddress((void**)&vhi, g_vhi);
    cudaGetSymbolAddress((void**)&vlo, g_vlo);
    cudaGetSymbolAddress((void**)&ctxhi, g_ctxhi);
    cudaGetSymbolAddress((void**)&ctxlo, g_ctxlo);
    cudaGetSymbolAddress((void**)&wThi, g_wThi);
    cudaGetSymbolAddress((void**)&wTlo, g_wTlo);
    cudaGetSymbolAddress((void**)&woThi, g_woThi);
    cudaGetSymbolAddress((void**)&woTlo, g_woTlo);

    cudaFuncSetAttribute(gemm_bf16p_128, cudaFuncAttributeMaxDynamicSharedMemorySize, GM2_SMEM);
    cudaFuncSetAttribute(flash_attn_mma3, cudaFuncAttributeMaxDynamicSharedMemorySize, FB_SMEM);

    // Pre-split x and weights (wq/wk/wv into one concatenated [3072,2048])
    {
        int n4 = S_LEN * D_MODEL / 4;
        split_kernel<<<(n4 + 255) / 256, 256>>>(x, xhi, xlo, n4);
    }
    transpose_split_kernel<<<dim3(D_MODEL / 32, D_MODEL / 32), dim3(32, 8)>>>(
        wq, wThi, wTlo, D_MODEL, D_MODEL);
    transpose_split_kernel<<<dim3(KV_D / 32, D_MODEL / 32), dim3(32, 8)>>>(
        wk, wThi + (size_t)D_MODEL * D_MODEL, wTlo + (size_t)D_MODEL * D_MODEL, D_MODEL, KV_D);
    transpose_split_kernel<<<dim3(KV_D / 32, D_MODEL / 32), dim3(32, 8)>>>(
        wv, wThi + (size_t)(D_MODEL + KV_D) * D_MODEL,
        wTlo + (size_t)(D_MODEL + KV_D) * D_MODEL, D_MODEL, KV_D);
    transpose_split_kernel<<<dim3(D_MODEL / 32, D_MODEL / 32), dim3(32, 8)>>>(
        wo, woThi, woTlo, D_MODEL, D_MODEL);

    // Merged QKV projection (128x128 tiles, 2 CTAs/SM)
    gemm_bf16p_128<<<dim3(QKV_N / 128, S_LEN / 128), 256, GM2_SMEM>>>(
        xhi, xlo, wThi, wTlo, nullptr,
        qhi, qlo, khi, klo, vhi, vlo, cosp, sinp,
        S_LEN, QKV_N, D_MODEL);

    // Flash attention (deferred-PV pipeline; writes ctx hi/lo planes)
    flash_attn_mma3<<<dim3((S_LEN / 128) * NH, 1), 256, FB_SMEM>>>(
        qhi, qlo, khi, klo, vhi, vlo, ctxhi, ctxlo);

    // Output projection (fp32 out)
    gemm_bf16p_128<<<dim3(D_MODEL / 128, S_LEN / 128), 256, GM2_SMEM>>>(
        ctxhi, ctxlo, woThi, woTlo, out,
        nullptr, nullptr, nullptr, nullptr, nullptr, nullptr, nullptr, nullptr,
        S_LEN, D_MODEL, D_MODEL);
}

// round 14
// speedup vs baseline: 1.1567x; 1.1233x over previous
#include <cuda_runtime.h>
#include <cuda_bf16.h>
#include <cuda_fp16.h>
#include <cstdint>

// Problem constants
#define S_LEN 4096
#define D_MODEL 2048
#define NH 16
#define NG 4
#define HD 128
#define KV_D (NG * HD)          // 512
#define QKV_N (D_MODEL + 2 * KV_D)  // 3072
#define SOFTMAX_SCALE 0.08838834764831845f  // 1/sqrt(128)

// bf16 hi/lo planes (+ fp16 V plane)
__device__ __nv_bfloat16 g_xhi[S_LEN * D_MODEL];
__device__ __nv_bfloat16 g_xlo[S_LEN * D_MODEL];
__device__ __nv_bfloat16 g_qhi[S_LEN * D_MODEL];
__device__ __nv_bfloat16 g_qlo[S_LEN * D_MODEL];
__device__ __nv_bfloat16 g_khi[S_LEN * KV_D];
__device__ __nv_bfloat16 g_klo[S_LEN * KV_D];
__device__ __half        g_vf[S_LEN * KV_D];
__device__ __nv_bfloat16 g_ctxhi[S_LEN * D_MODEL];
__device__ __nv_bfloat16 g_ctxlo[S_LEN * D_MODEL];
__device__ __nv_bfloat16 g_wThi[QKV_N * D_MODEL];   // rows: 0-2047 Q, 2048-2559 K, 2560-3071 V
__device__ __nv_bfloat16 g_wTlo[QKV_N * D_MODEL];
__device__ __nv_bfloat16 g_woThi[D_MODEL * D_MODEL];
__device__ __nv_bfloat16 g_woTlo[D_MODEL * D_MODEL];

// ---------------------------------------------------------------------------
// Helpers
// ---------------------------------------------------------------------------
__device__ __forceinline__ uint32_t smem_to_u32(const void* p) {
    uint32_t a;
    asm("{ .reg .u64 t; cvta.to.shared.u64 t, %1; cvt.u32.u64 %0, t; }"
        : "=r"(a) : "l"(p));
    return a;
}

__device__ __forceinline__ void cp_async16(uint32_t smem_addr, const void* gptr) {
    asm volatile("cp.async.cg.shared.global [%0], [%1], 16;" :: "r"(smem_addr), "l"(gptr));
}
__device__ __forceinline__ void cp_async_commit() {
    asm volatile("cp.async.commit_group;" ::: "memory");
}
template <int N>
__device__ __forceinline__ void cp_async_wait() {
    asm volatile("cp.async.wait_group %0;" :: "n"(N) : "memory");
}

__device__ __forceinline__ uint32_t pack_bf16(float x, float y) {
    uint32_t r;
    asm("cvt.rn.bf16x2.f32 %0, %1, %2;" : "=r"(r) : "f"(y), "f"(x));
    return r;
}
__device__ __forceinline__ uint32_t pack_f16(float x, float y) {
    uint32_t r;
    asm("cvt.rn.f16x2.f32 %0, %1, %2;" : "=r"(r) : "f"(y), "f"(x));
    return r;
}
__device__ __forceinline__ float bf16lo_f32(uint32_t h) { return __uint_as_float(h << 16); }
__device__ __forceinline__ float bf16hi_f32(uint32_t h) { return __uint_as_float(h & 0xffff0000u); }

__device__ __forceinline__ void split_bf16(float2 f, uint32_t& hi, uint32_t& lo) {
    hi = pack_bf16(f.x, f.y);
    float rx = f.x - bf16lo_f32(hi);
    float ry = f.y - bf16hi_f32(hi);
    lo = pack_bf16(rx, ry);
}

__device__ __forceinline__ void mma_bf16(float* c, const uint32_t* a, const uint32_t* b) {
    asm volatile(
        "mma.sync.aligned.m16n8k16.row.col.f32.bf16.bf16.f32 "
        "{%0,%1,%2,%3}, {%4,%5,%6,%7}, {%8,%9}, {%0,%1,%2,%3};"
        : "+f"(c[0]), "+f"(c[1]), "+f"(c[2]), "+f"(c[3])
        : "r"(a[0]), "r"(a[1]), "r"(a[2]), "r"(a[3]), "r"(b[0]), "r"(b[1]));
}
__device__ __forceinline__ void mma_f16(float* c, const uint32_t* a, const uint32_t* b) {
    asm volatile(
        "mma.sync.aligned.m16n8k16.row.col.f32.f16.f16.f32 "
        "{%0,%1,%2,%3}, {%4,%5,%6,%7}, {%8,%9}, {%0,%1,%2,%3};"
        : "+f"(c[0]), "+f"(c[1]), "+f"(c[2]), "+f"(c[3])
        : "r"(a[0]), "r"(a[1]), "r"(a[2]), "r"(a[3]), "r"(b[0]), "r"(b[1]));
}

__device__ __forceinline__ void ldsm_x4(uint32_t* r, uint32_t addr) {
    asm volatile("ldmatrix.sync.aligned.m8n8.x4.shared.b16 {%0,%1,%2,%3}, [%4];"
        : "=r"(r[0]), "=r"(r[1]), "=r"(r[2]), "=r"(r[3]) : "r"(addr));
}
__device__ __forceinline__ void ldsm_x4t(uint32_t* r, uint32_t addr) {
    asm volatile("ldmatrix.sync.aligned.m8n8.x4.trans.shared.b16 {%0,%1,%2,%3}, [%4];"
        : "=r"(r[0]), "=r"(r[1]), "=r"(r[2]), "=r"(r[3]) : "r"(addr));
}

// rope one pair in fp32 then split to bf16 planes
__device__ __forceinline__ void rope_pair_store(
        float a, float b, int sg, int d, float scale,
        const float* __restrict__ cosp, const float* __restrict__ sinp,
        __nv_bfloat16* __restrict__ hi, __nv_bfloat16* __restrict__ lo, size_t obase) {
    float c1 = cosp[sg * 128 + d],      s1 = sinp[sg * 128 + d];
    float c2 = cosp[sg * 128 + d + 64], s2 = sinp[sg * 128 + d + 64];
    float o1 = (a * c1 - b * s1) * scale;
    float o2 = (b * c2 + a * s2) * scale;
    __nv_bfloat16 h1 = __float2bfloat16(o1);
    __nv_bfloat16 L1 = __float2bfloat16(o1 - __bfloat162float(h1));
    __nv_bfloat16 h2 = __float2bfloat16(o2);
    __nv_bfloat16 L2 = __float2bfloat16(o2 - __bfloat162float(h2));
    hi[obase] = h1;      lo[obase] = L1;
    hi[obase + 64] = h2; lo[obase + 64] = L2;
}

// ---------------------------------------------------------------------------
// Split kernels
// ---------------------------------------------------------------------------
__global__ void split_kernel(const float* __restrict__ in,
                             __nv_bfloat16* __restrict__ hi,
                             __nv_bfloat16* __restrict__ lo,
                             int n4) {
    int idx = blockIdx.x * blockDim.x + threadIdx.x;
    if (idx >= n4) return;
    float4 v = ((const float4*)in)[idx];
    uint32_t h01, l01, h23, l23;
    split_bf16(make_float2(v.x, v.y), h01, l01);
    split_bf16(make_float2(v.z, v.w), h23, l23);
    ((uint2*)hi)[idx] = make_uint2(h01, h23);
    ((uint2*)lo)[idx] = make_uint2(l01, l23);
}

__global__ void transpose_split_kernel(const float* __restrict__ in,
                                       __nv_bfloat16* __restrict__ hiT,
                                       __nv_bfloat16* __restrict__ loT,
                                       int R, int C) {
    __shared__ float t[32][33];
    int c0 = blockIdx.x * 32, r0 = blockIdx.y * 32;
    int x = threadIdx.x, y = threadIdx.y;
#pragma unroll
    for (int i = y; i < 32; i += 8) t[i][x] = in[(size_t)(r0 + i) * C + c0 + x];
    __syncthreads();
#pragma unroll
    for (int i = y; i < 32; i += 8) {
        float v = t[x][i];
        __nv_bfloat16 h = __float2bfloat16(v);
        __nv_bfloat16 l = __float2bfloat16(v - __bfloat162float(h));
        size_t o = (size_t)(c0 + i) * R + r0 + x;
        hiT[o] = h;
        loT[o] = l;
    }
}

// ---------------------------------------------------------------------------
// GEMM 128x128, BK=32, 2-stage, SROW2=40, 2 CTAs/SM. Region epilogues:
//   C != null : fp32 store (O projection)
//   n0 < 2048          -> rope+scale+split to Q planes
//   2048 <= n0 < 2560  -> rope+split to K planes
//   n0 >= 2560         -> single fp16 plane V
// ---------------------------------------------------------------------------
#define SROW2 40
#define PL2 (128 * SROW2 * 2)
#define STG2 (4 * PL2)
#define GM2_SMEM (2 * STG2)          // 81920 B -> 2 CTAs/SM

__global__ __launch_bounds__(256, 2) void gemm_bf16p_128(
        const __nv_bfloat16* __restrict__ Ahi, const __nv_bfloat16* __restrict__ Alo,
        const __nv_bfloat16* __restrict__ Bhi, const __nv_bfloat16* __restrict__ Blo,
        float* __restrict__ C,
        __nv_bfloat16* __restrict__ Qhi, __nv_bfloat16* __restrict__ Qlo,
        __nv_bfloat16* __restrict__ Khi, __nv_bfloat16* __restrict__ Klo,
        __half* __restrict__ Vf,
        const float* __restrict__ cosp, const float* __restrict__ sinp,
        int M, int N, int K) {
    extern __shared__ char sm[];
    const uint32_t smem_u32 = smem_to_u32(sm);

    const int tid = threadIdx.x;
    const int wid = tid >> 5;
    const int lane = tid & 31;
    const int lr = lane & 7;
    const int lb8 = (lane >> 3) & 1;
    const int lb16 = (lane >> 4) & 1;
    const int wm = wid >> 2;
    const int wn = wid & 3;
    const int m0 = blockIdx.y * 128;
    const int n0 = blockIdx.x * 128;
    const int NS = K >> 5;

    const __nv_bfloat16* srcs[4] = {Ahi, Alo, Bhi, Blo};

    auto load_stage = [&](int s, int buf) {
        const int k0 = s << 5;
        const uint32_t base = smem_u32 + buf * STG2;
#pragma unroll
        for (int i = 0; i < 8; i++) {
            int c = tid + i * 256;
            int plane = c >> 9;
            int idx = c & 511;
            int row = idx >> 2;
            int ch = idx & 3;
            int grow = (plane < 2 ? m0 : n0) + row;
            const __nv_bfloat16* g = srcs[plane] + (size_t)grow * K + k0 + ch * 8;
            cp_async16(base + plane * PL2 + (row * SROW2 + ch * 8) * 2, g);
        }
    };

    float acc[4][4][4];
#pragma unroll
    for (int m = 0; m < 4; m++)
#pragma unroll
        for (int n = 0; n < 4; n++)
#pragma unroll
            for (int i = 0; i < 4; i++) acc[m][n][i] = 0.0f;

    load_stage(0, 0); cp_async_commit();
    load_stage(1, 1); cp_async_commit();

    const uint32_t a_off = ((wm * 64 + lr + lb8 * 8) * SROW2 + lb16 * 8) * 2;
    const uint32_t b_off = 2 * PL2 + ((wn * 32 + lr + lb16 * 8) * SROW2 + lb8 * 8) * 2;

    for (int s = 0; s < NS; s++) {
        const int buf = s & 1;
        cp_async_wait<1>();
        __syncthreads();

        const uint32_t base = smem_u32 + buf * STG2;

#pragma unroll
        for (int ks = 0; ks < 32; ks += 16) {
            uint32_t bhi[2][4], blo[2][4];
#pragma unroll
            for (int np = 0; np < 2; np++) {
                uint32_t addr = base + b_off + (np * 16 * SROW2 + ks) * 2;
                ldsm_x4(bhi[np], addr);
                ldsm_x4(blo[np], addr + PL2);
            }
#pragma unroll
            for (int m = 0; m < 4; m++) {
                uint32_t ahi[4], alo[4];
                uint32_t addr = base + a_off + (m * 16 * SROW2 + ks) * 2;
                ldsm_x4(ahi, addr);
                ldsm_x4(alo, addr + PL2);
#pragma unroll
                for (int n = 0; n < 4; n++) {
                    const uint32_t* bh = &bhi[n >> 1][(n & 1) * 2];
                    const uint32_t* bl = &blo[n >> 1][(n & 1) * 2];
                    mma_bf16(acc[m][n], ahi, bh);
                    mma_bf16(acc[m][n], ahi, bl);
                    mma_bf16(acc[m][n], alo, bh);
                }
            }
        }

        __syncthreads();
        if (s + 2 < NS) load_stage(s + 2, buf);
        cp_async_commit();
    }

    const int g = lane >> 2;
    const int tig = lane & 3;

    if (C) {
#pragma unroll
        for (int m = 0; m < 4; m++) {
            int r0 = m0 + wm * 64 + m * 16 + g;
            int r1 = r0 + 8;
#pragma unroll
            for (int n = 0; n < 4; n++) {
                int col = n0 + wn * 32 + n * 8 + tig * 2;
                *(float2*)(C + (size_t)r0 * N + col) = make_float2(acc[m][n][0], acc[m][n][1]);
                *(float2*)(C + (size_t)r1 * N + col) = make_float2(acc[m][n][2], acc[m][n][3]);
            }
        }
    } else if (n0 < D_MODEL + KV_D) {
        // Q or K region: rope + split via smem staging (fp32, stride 132)
        __nv_bfloat16* dhi = (n0 < D_MODEL) ? Qhi : Khi;
        __nv_bfloat16* dlo = (n0 < D_MODEL) ? Qlo : Klo;
        const int ld = (n0 < D_MODEL) ? D_MODEL : KV_D;
        const int colbase = (n0 < D_MODEL) ? n0 : (n0 - D_MODEL);
        const float scale = (n0 < D_MODEL) ? SOFTMAX_SCALE : 1.0f;

        float* st = (float*)sm;
        __syncthreads();
#pragma unroll
        for (int m = 0; m < 4; m++) {
            int rl = wm * 64 + m * 16 + g;
#pragma unroll
            for (int n = 0; n < 4; n++) {
                int col = wn * 32 + n * 8 + tig * 2;
                *(float2*)&st[rl * 132 + col] = make_float2(acc[m][n][0], acc[m][n][1]);
                *(float2*)&st[(rl + 8) * 132 + col] = make_float2(acc[m][n][2], acc[m][n][3]);
            }
        }
        __syncthreads();
#pragma unroll 4
        for (int p = 0; p < 32; p++) {
            int idx = tid + p * 256;
            int row = idx >> 6;
            int d = idx & 63;
            float a = st[row * 132 + d];
            float b = st[row * 132 + d + 64];
            int sg = m0 + row;
            size_t obase = (size_t)sg * ld + colbase + d;
            rope_pair_store(a, b, sg, d, scale, cosp, sinp, dhi, dlo, obase);
        }
    } else {
        // V region: single fp16 plane
#pragma unroll
        for (int m = 0; m < 4; m++) {
            int r0 = m0 + wm * 64 + m * 16 + g;
            int r1 = r0 + 8;
#pragma unroll
            for (int n = 0; n < 4; n++) {
                int col = n0 - (D_MODEL + KV_D) + wn * 32 + n * 8 + tig * 2;
                *(uint32_t*)&Vf[(size_t)r0 * KV_D + col] = pack_f16(acc[m][n][0], acc[m][n][1]);
                *(uint32_t*)&Vf[(size_t)r1 * KV_D + col] = pack_f16(acc[m][n][2], acc[m][n][3]);
            }
        }
    }
}

// ---------------------------------------------------------------------------
// Flash attention v4: deferred-PV pipeline; P/V in single fp16 (1 MMA per
// PV n-tile-half). QK unchanged (bf16x3).
// ---------------------------------------------------------------------------
#define QROW 136
#define FOFF_QLO 34816
#define FK0 69632                 // K stages: 2 x 34816 (hi@0, lo@17408)
#define FV0 (FK0 + 2 * 34816)     // 139264; V stages: 2 x 17408 (fp16 single)
#define FVSTG 17408
#define FB_SMEM (FV0 + 2 * FVSTG) // 174080

__global__ __launch_bounds__(256, 1) void flash_attn_mma4(
        const __nv_bfloat16* __restrict__ Qhi, const __nv_bfloat16* __restrict__ Qlo,
        const __nv_bfloat16* __restrict__ Khi, const __nv_bfloat16* __restrict__ Klo,
        const __half* __restrict__ Vf,
        __nv_bfloat16* __restrict__ Ohi, __nv_bfloat16* __restrict__ Olo) {
    extern __shared__ char sm[];
    const uint32_t smem_u32 = smem_to_u32(sm);

    const int b = blockIdx.x;
    const int qt = (int)(gridDim.x >> 4) - 1 - (b >> 4);
    const int h = b & 15;
    const int kvg = h >> 2;
    const int tid = threadIdx.x;
    const int w = tid >> 5;
    const int lane = tid & 31;
    const int lr = lane & 7;
    const int lb8 = (lane >> 3) & 1;
    const int lb16 = (lane >> 4) & 1;
    const int lg = lane >> 2;
    const int tig = lane & 3;
    const int q0 = qt * 128;
    const int qb = w * 16;

    auto load_k = [&](int jt, int buf) {
        const size_t rowbase = (size_t)(jt * 64) * KV_D + kvg * HD;
#pragma unroll
        for (int i = 0; i < 8; i++) {
            int c = tid + i * 256;
            int plane = c >> 10;
            int idx = c & 1023;
            int row = idx >> 4;
            int ch = idx & 15;
            const __nv_bfloat16* src = (plane ? Klo : Khi) + rowbase + (size_t)row * KV_D + ch * 8;
            cp_async16(smem_u32 + FK0 + buf * 34816 + plane * 17408 +
                       (row * QROW + ch * 8) * 2, src);
        }
    };
    auto load_v = [&](int jt, int buf) {
        const size_t rowbase = (size_t)(jt * 64) * KV_D + kvg * HD;
#pragma unroll
        for (int i = 0; i < 4; i++) {
            int c = tid + i * 256;     // 0..1023
            int row = c >> 4;
            int ch = c & 15;
            const __half* src = Vf + rowbase + (size_t)row * KV_D + ch * 8;
            cp_async16(smem_u32 + FV0 + buf * FVSTG + (row * QROW + ch * 8) * 2, src);
        }
    };

    // Prologue
#pragma unroll
    for (int i = 0; i < 16; i++) {
        int c = tid + i * 256;
        int plane = c >> 11;
        int idx = c & 2047;
        int row = idx >> 4;
        int ch = idx & 15;
        const __nv_bfloat16* src = (plane ? Qlo : Qhi) +
            (size_t)(q0 + row) * D_MODEL + h * HD + ch * 8;
        cp_async16(smem_u32 + plane * FOFF_QLO + (row * QROW + ch * 8) * 2, src);
    }
    load_k(0, 0);
    cp_async_commit();
    const int njt = 2 * qt + 2;
    load_k(1, 1);
    load_v(0, 0);
    cp_async_commit();

    const uint32_t qa_hi = smem_u32 + ((qb + lb8 * 8 + lr) * QROW + lb16 * 8) * 2;
    const uint32_t qa_lo = qa_hi + FOFF_QLO;
    const uint32_t k_off = ((lb16 * 8 + lr) * QROW + lb8 * 8) * 2;
    const uint32_t v_off = ((lb8 * 8 + lr) * QROW + lb16 * 8) * 2;

    float m0 = -1e30f, m1 = -1e30f, l0 = 0.0f, l1 = 0.0f;
    float oacc[16][4];
#pragma unroll
    for (int nt = 0; nt < 16; nt++)
#pragma unroll
        for (int j = 0; j < 4; j++) oacc[nt][j] = 0.0f;

    uint32_t pf[4][4];
    float ap0 = 1.0f, ap1 = 1.0f;
    int have_prev = 0;

    for (int jt = 0; jt < njt; jt++) {
        cp_async_wait<1>();
        __syncthreads();

        const uint32_t kb = smem_u32 + FK0 + (jt & 1) * 34816;
        const uint32_t vb_prev = smem_u32 + FV0 + ((jt & 1) ^ 1) * FVSTG;
        const bool active = (jt * 64 <= q0 + qb + 15);

        float sacc[8][4];
        if (active) {
#pragma unroll
            for (int nt = 0; nt < 8; nt++)
#pragma unroll
                for (int j = 0; j < 4; j++) sacc[nt][j] = 0.0f;

#pragma unroll
            for (int kc = 0; kc < 8; kc++) {
                uint32_t qhi[4], qlo[4];
                ldsm_x4(qhi, qa_hi + kc * 32);
                ldsm_x4(qlo, qa_lo + kc * 32);
#pragma unroll
                for (int ntp = 0; ntp < 4; ntp++) {
                    uint32_t khi[4], klo[4];
                    uint32_t ka = kb + k_off + ntp * (16 * QROW * 2) + kc * 32;
                    ldsm_x4(khi, ka);
                    ldsm_x4(klo, ka + 17408);
                    mma_bf16(sacc[2 * ntp], qhi, khi);
                    mma_bf16(sacc[2 * ntp], qhi, klo);
                    mma_bf16(sacc[2 * ntp], qlo, khi);
                    mma_bf16(sacc[2 * ntp + 1], qhi, khi + 2);
                    mma_bf16(sacc[2 * ntp + 1], qhi, klo + 2);
                    mma_bf16(sacc[2 * ntp + 1], qlo, khi + 2);
                }
            }
        }

        // Deferred PV of previous tile (fp16, 1 MMA per n-tile-half)
        if (have_prev) {
#pragma unroll
            for (int nt = 0; nt < 16; nt++) {
                oacc[nt][0] *= ap0;
                oacc[nt][1] *= ap0;
                oacc[nt][2] *= ap1;
                oacc[nt][3] *= ap1;
            }
#pragma unroll
            for (int kc = 0; kc < 4; kc++) {
#pragma unroll
                for (int ntp = 0; ntp < 8; ntp++) {
                    uint32_t vf[4];
                    uint32_t va = vb_prev + v_off + kc * (16 * QROW * 2) + ntp * 32;
                    ldsm_x4t(vf, va);
                    mma_f16(oacc[2 * ntp], pf[kc], vf);
                    mma_f16(oacc[2 * ntp + 1], pf[kc], vf + 2);
                }
            }
            have_prev = 0;
        }

        if (active) {
            if (jt * 64 + 63 > q0 + qb) {
#pragma unroll
                for (int nt = 0; nt < 8; nt++)
#pragma unroll
                    for (int j = 0; j < 4; j++) {
                        int gj = jt * 64 + nt * 8 + tig * 2 + (j & 1);
                        int gi = q0 + qb + lg + ((j >> 1) << 3);
                        if (gj > gi) sacc[nt][j] = -1e30f;
                    }
            }

            float cur0 = -1e30f, cur1 = -1e30f;
#pragma unroll
            for (int nt = 0; nt < 8; nt++) {
                cur0 = fmaxf(cur0, fmaxf(sacc[nt][0], sacc[nt][1]));
                cur1 = fmaxf(cur1, fmaxf(sacc[nt][2], sacc[nt][3]));
            }
            cur0 = fmaxf(cur0, __shfl_xor_sync(0xffffffffu, cur0, 1));
            cur0 = fmaxf(cur0, __shfl_xor_sync(0xffffffffu, cur0, 2));
            cur1 = fmaxf(cur1, __shfl_xor_sync(0xffffffffu, cur1, 1));
            cur1 = fmaxf(cur1, __shfl_xor_sync(0xffffffffu, cur1, 2));

            float mn0 = fmaxf(m0, cur0), mn1 = fmaxf(m1, cur1);
            ap0 = __expf(m0 - mn0);
            ap1 = __expf(m1 - mn1);
            m0 = mn0; m1 = mn1;

            float rs0 = 0.0f, rs1 = 0.0f;
#pragma unroll
            for (int nt = 0; nt < 8; nt++) {
                sacc[nt][0] = __expf(sacc[nt][0] - mn0);
                sacc[nt][1] = __expf(sacc[nt][1] - mn0);
                sacc[nt][2] = __expf(sacc[nt][2] - mn1);
                sacc[nt][3] = __expf(sacc[nt][3] - mn1);
                rs0 += sacc[nt][0] + sacc[nt][1];
                rs1 += sacc[nt][2] + sacc[nt][3];
            }
            rs0 += __shfl_xor_sync(0xffffffffu, rs0, 1);
            rs0 += __shfl_xor_sync(0xffffffffu, rs0, 2);
            rs1 += __shfl_xor_sync(0xffffffffu, rs1, 1);
            rs1 += __shfl_xor_sync(0xffffffffu, rs1, 2);
            l0 = l0 * ap0 + rs0;
            l1 = l1 * ap1 + rs1;

            // pack P (single fp16) for next-iteration PV
#pragma unroll
            for (int kc = 0; kc < 4; kc++) {
                pf[kc][0] = pack_f16(sacc[2 * kc][0], sacc[2 * kc][1]);
                pf[kc][1] = pack_f16(sacc[2 * kc][2], sacc[2 * kc][3]);
                pf[kc][2] = pack_f16(sacc[2 * kc + 1][0], sacc[2 * kc + 1][1]);
                pf[kc][3] = pack_f16(sacc[2 * kc + 1][2], sacc[2 * kc + 1][3]);
            }
            have_prev = 1;
        }

        __syncthreads();
        if (jt + 2 < njt) load_k(jt + 2, jt & 1);
        if (jt + 1 < njt) load_v(jt + 1, (jt + 1) & 1);
        cp_async_commit();
    }

    // Final deferred PV
    cp_async_wait<0>();
    __syncthreads();
    if (have_prev) {
        const uint32_t vb_last = smem_u32 + FV0 + ((njt - 1) & 1) * FVSTG;
#pragma unroll
        for (int nt = 0; nt < 16; nt++) {
            oacc[nt][0] *= ap0;
            oacc[nt][1] *= ap0;
            oacc[nt][2] *= ap1;
            oacc[nt][3] *= ap1;
        }
#pragma unroll
        for (int kc = 0; kc < 4; kc++) {
#pragma unroll
            for (int ntp = 0; ntp < 8; ntp++) {
                uint32_t vf[4];
                uint32_t va = vb_last + v_off + kc * (16 * QROW * 2) + ntp * 32;
                ldsm_x4t(vf, va);
                mma_f16(oacc[2 * ntp], pf[kc], vf);
                mma_f16(oacc[2 * ntp + 1], pf[kc], vf + 2);
            }
        }
    }

    float inv0 = 1.0f / l0;
    float inv1 = 1.0f / l1;
    int row0 = q0 + qb + lg;
    int row1 = row0 + 8;
#pragma unroll
    for (int nt = 0; nt < 16; nt++) {
        int col = h * HD + nt * 8 + tig * 2;
        uint32_t h0, lo0, h1, lo1;
        split_bf16(make_float2(oacc[nt][0] * inv0, oacc[nt][1] * inv0), h0, lo0);
        split_bf16(make_float2(oacc[nt][2] * inv1, oacc[nt][3] * inv1), h1, lo1);
        *(uint32_t*)&Ohi[(size_t)row0 * D_MODEL + col] = h0;
        *(uint32_t*)&Olo[(size_t)row0 * D_MODEL + col] = lo0;
        *(uint32_t*)&Ohi[(size_t)row1 * D_MODEL + col] = h1;
        *(uint32_t*)&Olo[(size_t)row1 * D_MODEL + col] = lo1;
    }
}

// ---------------------------------------------------------------------------
extern "C" void kernel_launch(void* const* d_in, const int* in_sizes, int n_in,
                              void* d_out, int out_size) {
    const float* x    = (const float*)d_in[0];
    const float* wq   = (const float*)d_in[2];
    const float* wk   = (const float*)d_in[3];
    const float* wv   = (const float*)d_in[4];
    const float* wo   = (const float*)d_in[5];
    const float* cosp = (const float*)d_in[6];
    const float* sinp = (const float*)d_in[7];
    float* out = (float*)d_out;

    __nv_bfloat16 *xhi, *xlo, *qhi, *qlo, *khi, *klo, *ctxhi, *ctxlo;
    __nv_bfloat16 *wThi, *wTlo, *woThi, *woTlo;
    __half *vf;
    cudaGetSymbolAddress((void**)&xhi, g_xhi);
    cudaGetSymbolAddress((void**)&xlo, g_xlo);
    cudaGetSymbolAddress((void**)&qhi, g_qhi);
    cudaGetSymbolAddress((void**)&qlo, g_qlo);
    cudaGetSymbolAddress((void**)&khi, g_khi);
    cudaGetSymbolAddress((void**)&klo, g_klo);
    cudaGetSymbolAddress((void**)&vf, g_vf);
    cudaGetSymbolAddress((void**)&ctxhi, g_ctxhi);
    cudaGetSymbolAddress((void**)&ctxlo, g_ctxlo);
    cudaGetSymbolAddress((void**)&wThi, g_wThi);
    cudaGetSymbolAddress((void**)&wTlo, g_wTlo);
    cudaGetSymbolAddress((void**)&woThi, g_woThi);
    cudaGetSymbolAddress((void**)&woTlo, g_woTlo);

    cudaFuncSetAttribute(gemm_bf16p_128, cudaFuncAttributeMaxDynamicSharedMemorySize, GM2_SMEM);
    cudaFuncSetAttribute(flash_attn_mma4, cudaFuncAttributeMaxDynamicSharedMemorySize, FB_SMEM);

    // Pre-split x and weights (wq/wk/wv into one concatenated [3072,2048])
    {
        int n4 = S_LEN * D_MODEL / 4;
        split_kernel<<<(n4 + 255) / 256, 256>>>(x, xhi, xlo, n4);
    }
    transpose_split_kernel<<<dim3(D_MODEL / 32, D_MODEL / 32), dim3(32, 8)>>>(
        wq, wThi, wTlo, D_MODEL, D_MODEL);
    transpose_split_kernel<<<dim3(KV_D / 32, D_MODEL / 32), dim3(32, 8)>>>(
        wk, wThi + (size_t)D_MODEL * D_MODEL, wTlo + (size_t)D_MODEL * D_MODEL, D_MODEL, KV_D);
    transpose_split_kernel<<<dim3(KV_D / 32, D_MODEL / 32), dim3(32, 8)>>>(
        wv, wThi + (size_t)(D_MODEL + KV_D) * D_MODEL,
        wTlo + (size_t)(D_MODEL + KV_D) * D_MODEL, D_MODEL, KV_D);
    transpose_split_kernel<<<dim3(D_MODEL / 32, D_MODEL / 32), dim3(32, 8)>>>(
        wo, woThi, woTlo, D_MODEL, D_MODEL);

    // Merged QKV projection (128x128 tiles, 2 CTAs/SM)
    gemm_bf16p_128<<<dim3(QKV_N / 128, S_LEN / 128), 256, GM2_SMEM>>>(
        xhi, xlo, wThi, wTlo, nullptr,
        qhi, qlo, khi, klo, vf, cosp, sinp,
        S_LEN, QKV_N, D_MODEL);

    // Flash attention (fp16 PV; writes ctx hi/lo planes)
    flash_attn_mma4<<<dim3((S_LEN / 128) * NH, 1), 256, FB_SMEM>>>(
        qhi, qlo, khi, klo, vf, ctxhi, ctxlo);

    // Output projection (fp32 out)
    gemm_bf16p_128<<<dim3(D_MODEL / 128, S_LEN / 128), 256, GM2_SMEM>>>(
        ctxhi, ctxlo, woThi, woTlo, out,
        nullptr, nullptr, nullptr, nullptr, nullptr, nullptr, nullptr,
        S_LEN, D_MODEL, D_MODEL);
}

// round 15
// speedup vs baseline: 1.1877x; 1.0268x over previous
#include <cuda_runtime.h>
#include <cuda_bf16.h>
#include <cuda_fp16.h>
#include <cstdint>

// Problem constants
#define S_LEN 4096
#define D_MODEL 2048
#define NH 16
#define NG 4
#define HD 128
#define KV_D (NG * HD)          // 512
#define QKV_N (D_MODEL + 2 * KV_D)  // 3072
#define SOFTMAX_SCALE 0.08838834764831845f  // 1/sqrt(128)

// planes
__device__ __nv_bfloat16 g_xhi[S_LEN * D_MODEL];
__device__ __nv_bfloat16 g_xlo[S_LEN * D_MODEL];
__device__ __half        g_qf[S_LEN * D_MODEL];     // Q: single fp16 (scale folded)
__device__ __half        g_khf[S_LEN * KV_D];       // K: fp16 hi
__device__ __half        g_klf[S_LEN * KV_D];       // K: fp16 lo
__device__ __half        g_vf[S_LEN * KV_D];        // V: single fp16
__device__ __nv_bfloat16 g_ctxhi[S_LEN * D_MODEL];
__device__ __nv_bfloat16 g_ctxlo[S_LEN * D_MODEL];
__device__ __nv_bfloat16 g_wThi[QKV_N * D_MODEL];   // rows: 0-2047 Q, 2048-2559 K, 2560-3071 V
__device__ __nv_bfloat16 g_wTlo[QKV_N * D_MODEL];
__device__ __nv_bfloat16 g_woThi[D_MODEL * D_MODEL];
__device__ __nv_bfloat16 g_woTlo[D_MODEL * D_MODEL];

// ---------------------------------------------------------------------------
// Helpers
// ---------------------------------------------------------------------------
__device__ __forceinline__ uint32_t smem_to_u32(const void* p) {
    uint32_t a;
    asm("{ .reg .u64 t; cvta.to.shared.u64 t, %1; cvt.u32.u64 %0, t; }"
        : "=r"(a) : "l"(p));
    return a;
}

__device__ __forceinline__ void cp_async16(uint32_t smem_addr, const void* gptr) {
    asm volatile("cp.async.cg.shared.global [%0], [%1], 16;" :: "r"(smem_addr), "l"(gptr));
}
__device__ __forceinline__ void cp_async_commit() {
    asm volatile("cp.async.commit_group;" ::: "memory");
}
template <int N>
__device__ __forceinline__ void cp_async_wait() {
    asm volatile("cp.async.wait_group %0;" :: "n"(N) : "memory");
}

__device__ __forceinline__ uint32_t pack_bf16(float x, float y) {
    uint32_t r;
    asm("cvt.rn.bf16x2.f32 %0, %1, %2;" : "=r"(r) : "f"(y), "f"(x));
    return r;
}
__device__ __forceinline__ uint32_t pack_f16(float x, float y) {
    uint32_t r;
    asm("cvt.rn.f16x2.f32 %0, %1, %2;" : "=r"(r) : "f"(y), "f"(x));
    return r;
}
__device__ __forceinline__ float bf16lo_f32(uint32_t h) { return __uint_as_float(h << 16); }
__device__ __forceinline__ float bf16hi_f32(uint32_t h) { return __uint_as_float(h & 0xffff0000u); }

__device__ __forceinline__ void split_bf16(float2 f, uint32_t& hi, uint32_t& lo) {
    hi = pack_bf16(f.x, f.y);
    float rx = f.x - bf16lo_f32(hi);
    float ry = f.y - bf16hi_f32(hi);
    lo = pack_bf16(rx, ry);
}

__device__ __forceinline__ void mma_bf16(float* c, const uint32_t* a, const uint32_t* b) {
    asm volatile(
        "mma.sync.aligned.m16n8k16.row.col.f32.bf16.bf16.f32 "
        "{%0,%1,%2,%3}, {%4,%5,%6,%7}, {%8,%9}, {%0,%1,%2,%3};"
        : "+f"(c[0]), "+f"(c[1]), "+f"(c[2]), "+f"(c[3])
        : "r"(a[0]), "r"(a[1]), "r"(a[2]), "r"(a[3]), "r"(b[0]), "r"(b[1]));
}
__device__ __forceinline__ void mma_f16(float* c, const uint32_t* a, const uint32_t* b) {
    asm volatile(
        "mma.sync.aligned.m16n8k16.row.col.f32.f16.f16.f32 "
        "{%0,%1,%2,%3}, {%4,%5,%6,%7}, {%8,%9}, {%0,%1,%2,%3};"
        : "+f"(c[0]), "+f"(c[1]), "+f"(c[2]), "+f"(c[3])
        : "r"(a[0]), "r"(a[1]), "r"(a[2]), "r"(a[3]), "r"(b[0]), "r"(b[1]));
}

__device__ __forceinline__ void ldsm_x4(uint32_t* r, uint32_t addr) {
    asm volatile("ldmatrix.sync.aligned.m8n8.x4.shared.b16 {%0,%1,%2,%3}, [%4];"
        : "=r"(r[0]), "=r"(r[1]), "=r"(r[2]), "=r"(r[3]) : "r"(addr));
}
__device__ __forceinline__ void ldsm_x4t(uint32_t* r, uint32_t addr) {
    asm volatile("ldmatrix.sync.aligned.m8n8.x4.trans.shared.b16 {%0,%1,%2,%3}, [%4];"
        : "=r"(r[0]), "=r"(r[1]), "=r"(r[2]), "=r"(r[3]) : "r"(addr));
}

// ---------------------------------------------------------------------------
// Split kernels
// ---------------------------------------------------------------------------
__global__ void split_kernel(const float* __restrict__ in,
                             __nv_bfloat16* __restrict__ hi,
                             __nv_bfloat16* __restrict__ lo,
                             int n4) {
    int idx = blockIdx.x * blockDim.x + threadIdx.x;
    if (idx >= n4) return;
    float4 v = ((const float4*)in)[idx];
    uint32_t h01, l01, h23, l23;
    split_bf16(make_float2(v.x, v.y), h01, l01);
    split_bf16(make_float2(v.z, v.w), h23, l23);
    ((uint2*)hi)[idx] = make_uint2(h01, h23);
    ((uint2*)lo)[idx] = make_uint2(l01, l23);
}

__global__ void transpose_split_kernel(const float* __restrict__ in,
                                       __nv_bfloat16* __restrict__ hiT,
                                       __nv_bfloat16* __restrict__ loT,
                                       int R, int C) {
    __shared__ float t[32][33];
    int c0 = blockIdx.x * 32, r0 = blockIdx.y * 32;
    int x = threadIdx.x, y = threadIdx.y;
#pragma unroll
    for (int i = y; i < 32; i += 8) t[i][x] = in[(size_t)(r0 + i) * C + c0 + x];
    __syncthreads();
#pragma unroll
    for (int i = y; i < 32; i += 8) {
        float v = t[x][i];
        __nv_bfloat16 h = __float2bfloat16(v);
        __nv_bfloat16 l = __float2bfloat16(v - __bfloat162float(h));
        size_t o = (size_t)(c0 + i) * R + r0 + x;
        hiT[o] = h;
        loT[o] = l;
    }
}

// ---------------------------------------------------------------------------
// GEMM 128x128, BK=32, 2-stage, SROW2=40, 2 CTAs/SM. Region epilogues:
//   C != null : fp32 store (O projection)
//   n0 < 2048          -> rope+scale, single fp16 Q plane
//   2048 <= n0 < 2560  -> rope, fp16 hi/lo K planes
//   n0 >= 2560         -> single fp16 V plane
// ---------------------------------------------------------------------------
#define SROW2 40
#define PL2 (128 * SROW2 * 2)
#define STG2 (4 * PL2)
#define GM2_SMEM (2 * STG2)          // 81920 B -> 2 CTAs/SM

__global__ __launch_bounds__(256, 2) void gemm_bf16p_128(
        const __nv_bfloat16* __restrict__ Ahi, const __nv_bfloat16* __restrict__ Alo,
        const __nv_bfloat16* __restrict__ Bhi, const __nv_bfloat16* __restrict__ Blo,
        float* __restrict__ C,
        __half* __restrict__ Qf,
        __half* __restrict__ Khf, __half* __restrict__ Klf,
        __half* __restrict__ Vf,
        const float* __restrict__ cosp, const float* __restrict__ sinp,
        int M, int N, int K) {
    extern __shared__ char sm[];
    const uint32_t smem_u32 = smem_to_u32(sm);

    const int tid = threadIdx.x;
    const int wid = tid >> 5;
    const int lane = tid & 31;
    const int lr = lane & 7;
    const int lb8 = (lane >> 3) & 1;
    const int lb16 = (lane >> 4) & 1;
    const int wm = wid >> 2;
    const int wn = wid & 3;
    const int m0 = blockIdx.y * 128;
    const int n0 = blockIdx.x * 128;
    const int NS = K >> 5;

    const __nv_bfloat16* srcs[4] = {Ahi, Alo, Bhi, Blo};

    auto load_stage = [&](int s, int buf) {
        const int k0 = s << 5;
        const uint32_t base = smem_u32 + buf * STG2;
#pragma unroll
        for (int i = 0; i < 8; i++) {
            int c = tid + i * 256;
            int plane = c >> 9;
            int idx = c & 511;
            int row = idx >> 2;
            int ch = idx & 3;
            int grow = (plane < 2 ? m0 : n0) + row;
            const __nv_bfloat16* g = srcs[plane] + (size_t)grow * K + k0 + ch * 8;
            cp_async16(base + plane * PL2 + (row * SROW2 + ch * 8) * 2, g);
        }
    };

    float acc[4][4][4];
#pragma unroll
    for (int m = 0; m < 4; m++)
#pragma unroll
        for (int n = 0; n < 4; n++)
#pragma unroll
            for (int i = 0; i < 4; i++) acc[m][n][i] = 0.0f;

    load_stage(0, 0); cp_async_commit();
    load_stage(1, 1); cp_async_commit();

    const uint32_t a_off = ((wm * 64 + lr + lb8 * 8) * SROW2 + lb16 * 8) * 2;
    const uint32_t b_off = 2 * PL2 + ((wn * 32 + lr + lb16 * 8) * SROW2 + lb8 * 8) * 2;

    for (int s = 0; s < NS; s++) {
        const int buf = s & 1;
        cp_async_wait<1>();
        __syncthreads();

        const uint32_t base = smem_u32 + buf * STG2;

#pragma unroll
        for (int ks = 0; ks < 32; ks += 16) {
            uint32_t bhi[2][4], blo[2][4];
#pragma unroll
            for (int np = 0; np < 2; np++) {
                uint32_t addr = base + b_off + (np * 16 * SROW2 + ks) * 2;
                ldsm_x4(bhi[np], addr);
                ldsm_x4(blo[np], addr + PL2);
            }
#pragma unroll
            for (int m = 0; m < 4; m++) {
                uint32_t ahi[4], alo[4];
                uint32_t addr = base + a_off + (m * 16 * SROW2 + ks) * 2;
                ldsm_x4(ahi, addr);
                ldsm_x4(alo, addr + PL2);
#pragma unroll
                for (int n = 0; n < 4; n++) {
                    const uint32_t* bh = &bhi[n >> 1][(n & 1) * 2];
                    const uint32_t* bl = &blo[n >> 1][(n & 1) * 2];
                    mma_bf16(acc[m][n], ahi, bh);
                    mma_bf16(acc[m][n], ahi, bl);
                    mma_bf16(acc[m][n], alo, bh);
                }
            }
        }

        __syncthreads();
        if (s + 2 < NS) load_stage(s + 2, buf);
        cp_async_commit();
    }

    const int g = lane >> 2;
    const int tig = lane & 3;

    if (C) {
#pragma unroll
        for (int m = 0; m < 4; m++) {
            int r0 = m0 + wm * 64 + m * 16 + g;
            int r1 = r0 + 8;
#pragma unroll
            for (int n = 0; n < 4; n++) {
                int col = n0 + wn * 32 + n * 8 + tig * 2;
                *(float2*)(C + (size_t)r0 * N + col) = make_float2(acc[m][n][0], acc[m][n][1]);
                *(float2*)(C + (size_t)r1 * N + col) = make_float2(acc[m][n][2], acc[m][n][3]);
            }
        }
    } else if (n0 < D_MODEL + KV_D) {
        // Q or K region: rope via smem staging (fp32, stride 132)
        const bool isQ = (n0 < D_MODEL);
        const int ld = isQ ? D_MODEL : KV_D;
        const int colbase = isQ ? n0 : (n0 - D_MODEL);
        const float scale = isQ ? SOFTMAX_SCALE : 1.0f;

        float* st = (float*)sm;
        __syncthreads();
#pragma unroll
        for (int m = 0; m < 4; m++) {
            int rl = wm * 64 + m * 16 + g;
#pragma unroll
            for (int n = 0; n < 4; n++) {
                int col = wn * 32 + n * 8 + tig * 2;
                *(float2*)&st[rl * 132 + col] = make_float2(acc[m][n][0], acc[m][n][1]);
                *(float2*)&st[(rl + 8) * 132 + col] = make_float2(acc[m][n][2], acc[m][n][3]);
            }
        }
        __syncthreads();
#pragma unroll 4
        for (int p = 0; p < 32; p++) {
            int idx = tid + p * 256;
            int row = idx >> 6;
            int d = idx & 63;
            float a = st[row * 132 + d];
            float b = st[row * 132 + d + 64];
            int sg = m0 + row;
            float c1 = cosp[sg * 128 + d],      s1 = sinp[sg * 128 + d];
            float c2 = cosp[sg * 128 + d + 64], s2 = sinp[sg * 128 + d + 64];
            float o1 = (a * c1 - b * s1) * scale;
            float o2 = (b * c2 + a * s2) * scale;
            size_t obase = (size_t)sg * ld + colbase + d;
            if (isQ) {
                Qf[obase]      = __float2half(o1);
                Qf[obase + 64] = __float2half(o2);
            } else {
                __half h1 = __float2half(o1);
                __half l1 = __float2half(o1 - __half2float(h1));
                __half h2 = __float2half(o2);
                __half l2 = __float2half(o2 - __half2float(h2));
                Khf[obase] = h1;      Klf[obase] = l1;
                Khf[obase + 64] = h2; Klf[obase + 64] = l2;
            }
        }
    } else {
        // V region: single fp16 plane
#pragma unroll
        for (int m = 0; m < 4; m++) {
            int r0 = m0 + wm * 64 + m * 16 + g;
            int r1 = r0 + 8;
#pragma unroll
            for (int n = 0; n < 4; n++) {
                int col = n0 - (D_MODEL + KV_D) + wn * 32 + n * 8 + tig * 2;
                *(uint32_t*)&Vf[(size_t)r0 * KV_D + col] = pack_f16(acc[m][n][0], acc[m][n][1]);
                *(uint32_t*)&Vf[(size_t)r1 * KV_D + col] = pack_f16(acc[m][n][2], acc[m][n][3]);
            }
        }
    }
}

// ---------------------------------------------------------------------------
// Flash attention v5: Q single fp16, K fp16 hi/lo (QK = 2 fp16 MMAs),
// P/V single fp16 (PV = 1 fp16 MMA), deferred-PV pipeline.
// smem: Q@0 (34816), K stages @34816 (2 x 34816: hi@0, lo@17408),
//       V stages @104448 (2 x 17408). Total 139264.
// ---------------------------------------------------------------------------
#define QROW 136
#define FK0 34816
#define FV0 104448
#define FVSTG 17408
#define FB_SMEM 139264

__global__ __launch_bounds__(256, 1) void flash_attn_mma5(
        const __half* __restrict__ Qf,
        const __half* __restrict__ Khf, const __half* __restrict__ Klf,
        const __half* __restrict__ Vf,
        __nv_bfloat16* __restrict__ Ohi, __nv_bfloat16* __restrict__ Olo) {
    extern __shared__ char sm[];
    const uint32_t smem_u32 = smem_to_u32(sm);

    const int b = blockIdx.x;
    const int qt = (int)(gridDim.x >> 4) - 1 - (b >> 4);
    const int h = b & 15;
    const int kvg = h >> 2;
    const int tid = threadIdx.x;
    const int w = tid >> 5;
    const int lane = tid & 31;
    const int lr = lane & 7;
    const int lb8 = (lane >> 3) & 1;
    const int lb16 = (lane >> 4) & 1;
    const int lg = lane >> 2;
    const int tig = lane & 3;
    const int q0 = qt * 128;
    const int qb = w * 16;

    auto load_k = [&](int jt, int buf) {
        const size_t rowbase = (size_t)(jt * 64) * KV_D + kvg * HD;
#pragma unroll
        for (int i = 0; i < 8; i++) {
            int c = tid + i * 256;
            int plane = c >> 10;
            int idx = c & 1023;
            int row = idx >> 4;
            int ch = idx & 15;
            const __half* src = (plane ? Klf : Khf) + rowbase + (size_t)row * KV_D + ch * 8;
            cp_async16(smem_u32 + FK0 + buf * 34816 + plane * 17408 +
                       (row * QROW + ch * 8) * 2, src);
        }
    };
    auto load_v = [&](int jt, int buf) {
        const size_t rowbase = (size_t)(jt * 64) * KV_D + kvg * HD;
#pragma unroll
        for (int i = 0; i < 4; i++) {
            int c = tid + i * 256;
            int row = c >> 4;
            int ch = c & 15;
            const __half* src = Vf + rowbase + (size_t)row * KV_D + ch * 8;
            cp_async16(smem_u32 + FV0 + buf * FVSTG + (row * QROW + ch * 8) * 2, src);
        }
    };

    // Prologue: Q (single plane) + K(0); then K(1) + V(0)
#pragma unroll
    for (int i = 0; i < 8; i++) {
        int c = tid + i * 256;
        int row = c >> 4;
        int ch = c & 15;
        const __half* src = Qf + (size_t)(q0 + row) * D_MODEL + h * HD + ch * 8;
        cp_async16(smem_u32 + (row * QROW + ch * 8) * 2, src);
    }
    load_k(0, 0);
    cp_async_commit();
    const int njt = 2 * qt + 2;
    load_k(1, 1);
    load_v(0, 0);
    cp_async_commit();

    const uint32_t qa = smem_u32 + ((qb + lb8 * 8 + lr) * QROW + lb16 * 8) * 2;
    const uint32_t k_off = ((lb16 * 8 + lr) * QROW + lb8 * 8) * 2;
    const uint32_t v_off = ((lb8 * 8 + lr) * QROW + lb16 * 8) * 2;

    float m0 = -1e30f, m1 = -1e30f, l0 = 0.0f, l1 = 0.0f;
    float oacc[16][4];
#pragma unroll
    for (int nt = 0; nt < 16; nt++)
#pragma unroll
        for (int j = 0; j < 4; j++) oacc[nt][j] = 0.0f;

    uint32_t pf[4][4];
    float ap0 = 1.0f, ap1 = 1.0f;
    int have_prev = 0;

    for (int jt = 0; jt < njt; jt++) {
        cp_async_wait<1>();
        __syncthreads();

        const uint32_t kb = smem_u32 + FK0 + (jt & 1) * 34816;
        const uint32_t vb_prev = smem_u32 + FV0 + ((jt & 1) ^ 1) * FVSTG;
        const bool active = (jt * 64 <= q0 + qb + 15);

        float sacc[8][4];
        if (active) {
#pragma unroll
            for (int nt = 0; nt < 8; nt++)
#pragma unroll
                for (int j = 0; j < 4; j++) sacc[nt][j] = 0.0f;

#pragma unroll
            for (int kc = 0; kc < 8; kc++) {
                uint32_t qf4[4];
                ldsm_x4(qf4, qa + kc * 32);
#pragma unroll
                for (int ntp = 0; ntp < 4; ntp++) {
                    uint32_t khf4[4], klf4[4];
                    uint32_t ka = kb + k_off + ntp * (16 * QROW * 2) + kc * 32;
                    ldsm_x4(khf4, ka);
                    ldsm_x4(klf4, ka + 17408);
                    mma_f16(sacc[2 * ntp], qf4, khf4);
                    mma_f16(sacc[2 * ntp], qf4, klf4);
                    mma_f16(sacc[2 * ntp + 1], qf4, khf4 + 2);
                    mma_f16(sacc[2 * ntp + 1], qf4, klf4 + 2);
                }
            }
        }

        // Deferred PV of previous tile (fp16)
        if (have_prev) {
#pragma unroll
            for (int nt = 0; nt < 16; nt++) {
                oacc[nt][0] *= ap0;
                oacc[nt][1] *= ap0;
                oacc[nt][2] *= ap1;
                oacc[nt][3] *= ap1;
            }
#pragma unroll
            for (int kc = 0; kc < 4; kc++) {
#pragma unroll
                for (int ntp = 0; ntp < 8; ntp++) {
                    uint32_t vf4[4];
                    uint32_t va = vb_prev + v_off + kc * (16 * QROW * 2) + ntp * 32;
                    ldsm_x4t(vf4, va);
                    mma_f16(oacc[2 * ntp], pf[kc], vf4);
                    mma_f16(oacc[2 * ntp + 1], pf[kc], vf4 + 2);
                }
            }
            have_prev = 0;
        }

        if (active) {
            if (jt * 64 + 63 > q0 + qb) {
#pragma unroll
                for (int nt = 0; nt < 8; nt++)
#pragma unroll
                    for (int j = 0; j < 4; j++) {
                        int gj = jt * 64 + nt * 8 + tig * 2 + (j & 1);
                        int gi = q0 + qb + lg + ((j >> 1) << 3);
                        if (gj > gi) sacc[nt][j] = -1e30f;
                    }
            }

            float cur0 = -1e30f, cur1 = -1e30f;
#pragma unroll
            for (int nt = 0; nt < 8; nt++) {
                cur0 = fmaxf(cur0, fmaxf(sacc[nt][0], sacc[nt][1]));
                cur1 = fmaxf(cur1, fmaxf(sacc[nt][2], sacc[nt][3]));
            }
            cur0 = fmaxf(cur0, __shfl_xor_sync(0xffffffffu, cur0, 1));
            cur0 = fmaxf(cur0, __shfl_xor_sync(0xffffffffu, cur0, 2));
            cur1 = fmaxf(cur1, __shfl_xor_sync(0xffffffffu, cur1, 1));
            cur1 = fmaxf(cur1, __shfl_xor_sync(0xffffffffu, cur1, 2));

            float mn0 = fmaxf(m0, cur0), mn1 = fmaxf(m1, cur1);
            ap0 = __expf(m0 - mn0);
            ap1 = __expf(m1 - mn1);
            m0 = mn0; m1 = mn1;

            float rs0 = 0.0f, rs1 = 0.0f;
#pragma unroll
            for (int nt = 0; nt < 8; nt++) {
                sacc[nt][0] = __expf(sacc[nt][0] - mn0);
                sacc[nt][1] = __expf(sacc[nt][1] - mn0);
                sacc[nt][2] = __expf(sacc[nt][2] - mn1);
                sacc[nt][3] = __expf(sacc[nt][3] - mn1);
                rs0 += sacc[nt][0] + sacc[nt][1];
                rs1 += sacc[nt][2] + sacc[nt][3];
            }
            rs0 += __shfl_xor_sync(0xffffffffu, rs0, 1);
            rs0 += __shfl_xor_sync(0xffffffffu, rs0, 2);
            rs1 += __shfl_xor_sync(0xffffffffu, rs1, 1);
            rs1 += __shfl_xor_sync(0xffffffffu, rs1, 2);
            l0 = l0 * ap0 + rs0;
            l1 = l1 * ap1 + rs1;

            // pack P (fp16) for next-iteration PV
#pragma unroll
            for (int kc = 0; kc < 4; kc++) {
                pf[kc][0] = pack_f16(sacc[2 * kc][0], sacc[2 * kc][1]);
                pf[kc][1] = pack_f16(sacc[2 * kc][2], sacc[2 * kc][3]);
                pf[kc][2] = pack_f16(sacc[2 * kc + 1][0], sacc[2 * kc + 1][1]);
                pf[kc][3] = pack_f16(sacc[2 * kc + 1][2], sacc[2 * kc + 1][3]);
            }
            have_prev = 1;
        }

        __syncthreads();
        if (jt + 2 < njt) load_k(jt + 2, jt & 1);
        if (jt + 1 < njt) load_v(jt + 1, (jt + 1) & 1);
        cp_async_commit();
    }

    // Final deferred PV
    cp_async_wait<0>();
    __syncthreads();
    if (have_prev) {
        const uint32_t vb_last = smem_u32 + FV0 + ((njt - 1) & 1) * FVSTG;
#pragma unroll
        for (int nt = 0; nt < 16; nt++) {
            oacc[nt][0] *= ap0;
            oacc[nt][1] *= ap0;
            oacc[nt][2] *= ap1;
            oacc[nt][3] *= ap1;
        }
#pragma unroll
        for (int kc = 0; kc < 4; kc++) {
#pragma unroll
            for (int ntp = 0; ntp < 8; ntp++) {
                uint32_t vf4[4];
                uint32_t va = vb_last + v_off + kc * (16 * QROW * 2) + ntp * 32;
                ldsm_x4t(vf4, va);
                mma_f16(oacc[2 * ntp], pf[kc], vf4);
                mma_f16(oacc[2 * ntp + 1], pf[kc], vf4 + 2);
            }
        }
    }

    float inv0 = 1.0f / l0;
    float inv1 = 1.0f / l1;
    int row0 = q0 + qb + lg;
    int row1 = row0 + 8;
#pragma unroll
    for (int nt = 0; nt < 16; nt++) {
        int col = h * HD + nt * 8 + tig * 2;
        uint32_t h0, lo0, h1, lo1;
        split_bf16(make_float2(oacc[nt][0] * inv0, oacc[nt][1] * inv0), h0, lo0);
        split_bf16(make_float2(oacc[nt][2] * inv1, oacc[nt][3] * inv1), h1, lo1);
        *(uint32_t*)&Ohi[(size_t)row0 * D_MODEL + col] = h0;
        *(uint32_t*)&Olo[(size_t)row0 * D_MODEL + col] = lo0;
        *(uint32_t*)&Ohi[(size_t)row1 * D_MODEL + col] = h1;
        *(uint32_t*)&Olo[(size_t)row1 * D_MODEL + col] = lo1;
    }
}

// ---------------------------------------------------------------------------
extern "C" void kernel_launch(void* const* d_in, const int* in_sizes, int n_in,
                              void* d_out, int out_size) {
    const float* x    = (const float*)d_in[0];
    const float* wq   = (const float*)d_in[2];
    const float* wk   = (const float*)d_in[3];
    const float* wv   = (const float*)d_in[4];
    const float* wo   = (const float*)d_in[5];
    const float* cosp = (const float*)d_in[6];
    const float* sinp = (const float*)d_in[7];
    float* out = (float*)d_out;

    __nv_bfloat16 *xhi, *xlo, *ctxhi, *ctxlo, *wThi, *wTlo, *woThi, *woTlo;
    __half *qf, *khf, *klf, *vf;
    cudaGetSymbolAddress((void**)&xhi, g_xhi);
    cudaGetSymbolAddress((void**)&xlo, g_xlo);
    cudaGetSymbolAddress((void**)&qf, g_qf);
    cudaGetSymbolAddress((void**)&khf, g_khf);
    cudaGetSymbolAddress((void**)&klf, g_klf);
    cudaGetSymbolAddress((void**)&vf, g_vf);
    cudaGetSymbolAddress((void**)&ctxhi, g_ctxhi);
    cudaGetSymbolAddress((void**)&ctxlo, g_ctxlo);
    cudaGetSymbolAddress((void**)&wThi, g_wThi);
    cudaGetSymbolAddress((void**)&wTlo, g_wTlo);
    cudaGetSymbolAddress((void**)&woThi, g_woThi);
    cudaGetSymbolAddress((void**)&woTlo, g_woTlo);

    cudaFuncSetAttribute(gemm_bf16p_128, cudaFuncAttributeMaxDynamicSharedMemorySize, GM2_SMEM);
    cudaFuncSetAttribute(flash_attn_mma5, cudaFuncAttributeMaxDynamicSharedMemorySize, FB_SMEM);

    // Pre-split x and weights (wq/wk/wv into one concatenated [3072,2048])
    {
        int n4 = S_LEN * D_MODEL / 4;
        split_kernel<<<(n4 + 255) / 256, 256>>>(x, xhi, xlo, n4);
    }
    transpose_split_kernel<<<dim3(D_MODEL / 32, D_MODEL / 32), dim3(32, 8)>>>(
        wq, wThi, wTlo, D_MODEL, D_MODEL);
    transpose_split_kernel<<<dim3(KV_D / 32, D_MODEL / 32), dim3(32, 8)>>>(
        wk, wThi + (size_t)D_MODEL * D_MODEL, wTlo + (size_t)D_MODEL * D_MODEL, D_MODEL, KV_D);
    transpose_split_kernel<<<dim3(KV_D / 32, D_MODEL / 32), dim3(32, 8)>>>(
        wv, wThi + (size_t)(D_MODEL + KV_D) * D_MODEL,
        wTlo + (size_t)(D_MODEL + KV_D) * D_MODEL, D_MODEL, KV_D);
    transpose_split_kernel<<<dim3(D_MODEL / 32, D_MODEL / 32), dim3(32, 8)>>>(
        wo, woThi, woTlo, D_MODEL, D_MODEL);

    // Merged QKV projection (128x128 tiles, 2 CTAs/SM)
    gemm_bf16p_128<<<dim3(QKV_N / 128, S_LEN / 128), 256, GM2_SMEM>>>(
        xhi, xlo, wThi, wTlo, nullptr,
        qf, khf, klf, vf, cosp, sinp,
        S_LEN, QKV_N, D_MODEL);

    // Flash attention (fp16 QK x2 + fp16 PV; writes ctx hi/lo planes)
    flash_attn_mma5<<<dim3((S_LEN / 128) * NH, 1), 256, FB_SMEM>>>(
        qf, khf, klf, vf, ctxhi, ctxlo);

    // Output projection (fp32 out)
    gemm_bf16p_128<<<dim3(D_MODEL / 128, S_LEN / 128), 256, GM2_SMEM>>>(
        ctxhi, ctxlo, woThi, woTlo, out,
        nullptr, nullptr, nullptr, nullptr, nullptr, nullptr,
        S_LEN, D_MODEL, D_MODEL);
}

// round 17
// speedup vs baseline: 1.5229x; 1.2822x over previous
#include <cuda_runtime.h>
#include <cuda_bf16.h>
#include <cuda_fp16.h>
#include <cstdint>

// Problem constants
#define S_LEN 4096
#define D_MODEL 2048
#define NH 16
#define NG 4
#define HD 128
#define KV_D (NG * HD)          // 512
#define QKV_N (D_MODEL + 2 * KV_D)  // 3072
#define SOFTMAX_SCALE 0.08838834764831845f  // 1/sqrt(128)

// fp16 planes
__device__ __half g_xf[S_LEN * D_MODEL];       // x: single fp16
__device__ __half g_qf[S_LEN * D_MODEL];       // Q: single fp16 (scale folded)
__device__ __half g_khf[S_LEN * KV_D];         // K hi
__device__ __half g_klf[S_LEN * KV_D];         // K lo
__device__ __half g_vf[S_LEN * KV_D];          // V single
__device__ __half g_ctxf[S_LEN * D_MODEL];     // ctx single
__device__ __half g_wThf[QKV_N * D_MODEL];     // QKV weights hi (rows: Q,K,V)
__device__ __half g_wTlf[QKV_N * D_MODEL];     // QKV weights lo
__device__ __half g_woThf[D_MODEL * D_MODEL];
__device__ __half g_woTlf[D_MODEL * D_MODEL];

// ---------------------------------------------------------------------------
// Helpers
// ---------------------------------------------------------------------------
__device__ __forceinline__ uint32_t smem_to_u32(const void* p) {
    uint32_t a;
    asm("{ .reg .u64 t; cvta.to.shared.u64 t, %1; cvt.u32.u64 %0, t; }"
        : "=r"(a) : "l"(p));
    return a;
}

__device__ __forceinline__ void cp_async16(uint32_t smem_addr, const void* gptr) {
    asm volatile("cp.async.cg.shared.global [%0], [%1], 16;" :: "r"(smem_addr), "l"(gptr));
}
__device__ __forceinline__ void cp_async_commit() {
    asm volatile("cp.async.commit_group;" ::: "memory");
}
template <int N>
__device__ __forceinline__ void cp_async_wait() {
    asm volatile("cp.async.wait_group %0;" :: "n"(N) : "memory");
}

__device__ __forceinline__ uint32_t pack_f16(float x, float y) {
    uint32_t r;
    asm("cvt.rn.f16x2.f32 %0, %1, %2;" : "=r"(r) : "f"(y), "f"(x));
    return r;
}

__device__ __forceinline__ void mma_f16(float* c, const uint32_t* a, const uint32_t* b) {
    asm volatile(
        "mma.sync.aligned.m16n8k16.row.col.f32.f16.f16.f32 "
        "{%0,%1,%2,%3}, {%4,%5,%6,%7}, {%8,%9}, {%0,%1,%2,%3};"
        : "+f"(c[0]), "+f"(c[1]), "+f"(c[2]), "+f"(c[3])
        : "r"(a[0]), "r"(a[1]), "r"(a[2]), "r"(a[3]), "r"(b[0]), "r"(b[1]));
}

__device__ __forceinline__ void ldsm_x4(uint32_t* r, uint32_t addr) {
    asm volatile("ldmatrix.sync.aligned.m8n8.x4.shared.b16 {%0,%1,%2,%3}, [%4];"
        : "=r"(r[0]), "=r"(r[1]), "=r"(r[2]), "=r"(r[3]) : "r"(addr));
}
__device__ __forceinline__ void ldsm_x4t(uint32_t* r, uint32_t addr) {
    asm volatile("ldmatrix.sync.aligned.m8n8.x4.trans.shared.b16 {%0,%1,%2,%3}, [%4];"
        : "=r"(r[0]), "=r"(r[1]), "=r"(r[2]), "=r"(r[3]) : "r"(addr));
}

// ---------------------------------------------------------------------------
// Convert / split kernels
// ---------------------------------------------------------------------------
__global__ void tofp16_kernel(const float* __restrict__ in,
                              __half* __restrict__ outp, int n4) {
    int idx = blockIdx.x * blockDim.x + threadIdx.x;
    if (idx >= n4) return;
    float4 v = ((const float4*)in)[idx];
    ((uint2*)outp)[idx] = make_uint2(pack_f16(v.x, v.y), pack_f16(v.z, v.w));
}

// transpose + fp16 hi/lo split: out[C,R] = in[R,C]
__global__ void transpose_split_f16_kernel(const float* __restrict__ in,
                                           __half* __restrict__ hiT,
                                           __half* __restrict__ loT,
                                           int R, int C) {
    __shared__ float t[32][33];
    int c0 = blockIdx.x * 32, r0 = blockIdx.y * 32;
    int x = threadIdx.x, y = threadIdx.y;
#pragma unroll
    for (int i = y; i < 32; i += 8) t[i][x] = in[(size_t)(r0 + i) * C + c0 + x];
    __syncthreads();
#pragma unroll
    for (int i = y; i < 32; i += 8) {
        float v = t[x][i];
        __half h = __float2half(v);
        __half l = __float2half(v - __half2float(h));
        size_t o = (size_t)(c0 + i) * R + r0 + x;
        hiT[o] = h;
        loT[o] = l;
    }
}

// ---------------------------------------------------------------------------
// GEMM 128x128, BK=32, 2-stage: A single fp16, B fp16 hi/lo (2 MMAs/term).
// smem pipeline: A@0, Bhi@PL2, Blo@2*PL2; stage 30720 B; 2 stages = 61440.
// Epilogue rope staging needs 128*132*4 = 67584 B -> GM3_SMEM = 67584
// (the stage area is reused after the mainloop; 2 CTAs/SM still fits).
// ---------------------------------------------------------------------------
#define SROW2 40
#define PL2 (128 * SROW2 * 2)        // 10240
#define STG3 (3 * PL2)               // 30720
#define GM3_SMEM 67584               // max(2*STG3=61440, 128*132*4=67584)

__global__ __launch_bounds__(256, 2) void gemm_f16_128(
        const __half* __restrict__ Af,
        const __half* __restrict__ Bhf, const __half* __restrict__ Blf,
        float* __restrict__ C,
        __half* __restrict__ Qf,
        __half* __restrict__ Khf, __half* __restrict__ Klf,
        __half* __restrict__ Vf,
        const float* __restrict__ cosp, const float* __restrict__ sinp,
        int M, int N, int K) {
    extern __shared__ char sm[];
    const uint32_t smem_u32 = smem_to_u32(sm);

    const int tid = threadIdx.x;
    const int wid = tid >> 5;
    const int lane = tid & 31;
    const int lr = lane & 7;
    const int lb8 = (lane >> 3) & 1;
    const int lb16 = (lane >> 4) & 1;
    const int wm = wid >> 2;
    const int wn = wid & 3;
    const int m0 = blockIdx.y * 128;
    const int n0 = blockIdx.x * 128;
    const int NS = K >> 5;

    auto load_stage = [&](int s, int buf) {
        const int k0 = s << 5;
        const uint32_t base = smem_u32 + buf * STG3;
#pragma unroll
        for (int i = 0; i < 6; i++) {
            int c = tid + i * 256;       // 0..1535
            int plane = c >> 9;          // 0=A, 1=Bhi, 2=Blo
            int idx = c & 511;
            int row = idx >> 2;
            int ch = idx & 3;
            const __half* g;
            if (plane == 0)      g = Af  + (size_t)(m0 + row) * K + k0 + ch * 8;
            else if (plane == 1) g = Bhf + (size_t)(n0 + row) * K + k0 + ch * 8;
            else                 g = Blf + (size_t)(n0 + row) * K + k0 + ch * 8;
            cp_async16(base + plane * PL2 + (row * SROW2 + ch * 8) * 2, g);
        }
    };

    float acc[4][4][4];
#pragma unroll
    for (int m = 0; m < 4; m++)
#pragma unroll
        for (int n = 0; n < 4; n++)
#pragma unroll
            for (int i = 0; i < 4; i++) acc[m][n][i] = 0.0f;

    load_stage(0, 0); cp_async_commit();
    load_stage(1, 1); cp_async_commit();

    const uint32_t a_off = ((wm * 64 + lr + lb8 * 8) * SROW2 + lb16 * 8) * 2;
    const uint32_t b_off = PL2 + ((wn * 32 + lr + lb16 * 8) * SROW2 + lb8 * 8) * 2;

    for (int s = 0; s < NS; s++) {
        const int buf = s & 1;
        cp_async_wait<1>();
        __syncthreads();

        const uint32_t base = smem_u32 + buf * STG3;

#pragma unroll
        for (int ks = 0; ks < 32; ks += 16) {
            uint32_t bh[2][4], bl[2][4];
#pragma unroll
            for (int np = 0; np < 2; np++) {
                uint32_t addr = base + b_off + (np * 16 * SROW2 + ks) * 2;
                ldsm_x4(bh[np], addr);
                ldsm_x4(bl[np], addr + PL2);
            }
#pragma unroll
            for (int m = 0; m < 4; m++) {
                uint32_t af[4];
                ldsm_x4(af, base + a_off + (m * 16 * SROW2 + ks) * 2);
#pragma unroll
                for (int n = 0; n < 4; n++) {
                    const uint32_t* bhs = &bh[n >> 1][(n & 1) * 2];
                    const uint32_t* bls = &bl[n >> 1][(n & 1) * 2];
                    mma_f16(acc[m][n], af, bhs);
                    mma_f16(acc[m][n], af, bls);
                }
            }
        }

        __syncthreads();
        if (s + 2 < NS) load_stage(s + 2, buf);
        cp_async_commit();
    }

    const int g = lane >> 2;
    const int tig = lane & 3;

    if (C) {
#pragma unroll
        for (int m = 0; m < 4; m++) {
            int r0 = m0 + wm * 64 + m * 16 + g;
            int r1 = r0 + 8;
#pragma unroll
            for (int n = 0; n < 4; n++) {
                int col = n0 + wn * 32 + n * 8 + tig * 2;
                *(float2*)(C + (size_t)r0 * N + col) = make_float2(acc[m][n][0], acc[m][n][1]);
                *(float2*)(C + (size_t)r1 * N + col) = make_float2(acc[m][n][2], acc[m][n][3]);
            }
        }
    } else if (n0 < D_MODEL + KV_D) {
        // Q or K region: rope via smem staging (fp32, stride 132 = 67584 B)
        const bool isQ = (n0 < D_MODEL);
        const int ld = isQ ? D_MODEL : KV_D;
        const int colbase = isQ ? n0 : (n0 - D_MODEL);
        const float scale = isQ ? SOFTMAX_SCALE : 1.0f;

        float* st = (float*)sm;
        cp_async_wait<0>();
        __syncthreads();
#pragma unroll
        for (int m = 0; m < 4; m++) {
            int rl = wm * 64 + m * 16 + g;
#pragma unroll
            for (int n = 0; n < 4; n++) {
                int col = wn * 32 + n * 8 + tig * 2;
                *(float2*)&st[rl * 132 + col] = make_float2(acc[m][n][0], acc[m][n][1]);
                *(float2*)&st[(rl + 8) * 132 + col] = make_float2(acc[m][n][2], acc[m][n][3]);
            }
        }
        __syncthreads();
#pragma unroll 4
        for (int p = 0; p < 32; p++) {
            int idx = tid + p * 256;
            int row = idx >> 6;
            int d = idx & 63;
            float a = st[row * 132 + d];
            float b = st[row * 132 + d + 64];
            int sg = m0 + row;
            float c1 = cosp[sg * 128 + d],      s1 = sinp[sg * 128 + d];
            float c2 = cosp[sg * 128 + d + 64], s2 = sinp[sg * 128 + d + 64];
            float o1 = (a * c1 - b * s1) * scale;
            float o2 = (b * c2 + a * s2) * scale;
            size_t obase = (size_t)sg * ld + colbase + d;
            if (isQ) {
                Qf[obase]      = __float2half(o1);
                Qf[obase + 64] = __float2half(o2);
            } else {
                __half h1 = __float2half(o1);
                __half l1 = __float2half(o1 - __half2float(h1));
                __half h2 = __float2half(o2);
                __half l2 = __float2half(o2 - __half2float(h2));
                Khf[obase] = h1;      Klf[obase] = l1;
                Khf[obase + 64] = h2; Klf[obase + 64] = l2;
            }
        }
    } else {
        // V region: single fp16 plane
#pragma unroll
        for (int m = 0; m < 4; m++) {
            int r0 = m0 + wm * 64 + m * 16 + g;
            int r1 = r0 + 8;
#pragma unroll
            for (int n = 0; n < 4; n++) {
                int col = n0 - (D_MODEL + KV_D) + wn * 32 + n * 8 + tig * 2;
                *(uint32_t*)&Vf[(size_t)r0 * KV_D + col] = pack_f16(acc[m][n][0], acc[m][n][1]);
                *(uint32_t*)&Vf[(size_t)r1 * KV_D + col] = pack_f16(acc[m][n][2], acc[m][n][3]);
            }
        }
    }
}

// ---------------------------------------------------------------------------
// Flash attention v6: Q fp16, K fp16 hi/lo (QK = 2 MMAs), P/V fp16 (PV = 1),
// deferred-PV pipeline, ctx written as single fp16 plane.
// ---------------------------------------------------------------------------
#define QROW 136
#define FK0 34816
#define FV0 104448
#define FVSTG 17408
#define FB_SMEM 139264

__global__ __launch_bounds__(256, 1) void flash_attn_mma6(
        const __half* __restrict__ Qf,
        const __half* __restrict__ Khf, const __half* __restrict__ Klf,
        const __half* __restrict__ Vf,
        __half* __restrict__ Of) {
    extern __shared__ char sm[];
    const uint32_t smem_u32 = smem_to_u32(sm);

    const int b = blockIdx.x;
    const int qt = (int)(gridDim.x >> 4) - 1 - (b >> 4);
    const int h = b & 15;
    const int kvg = h >> 2;
    const int tid = threadIdx.x;
    const int w = tid >> 5;
    const int lane = tid & 31;
    const int lr = lane & 7;
    const int lb8 = (lane >> 3) & 1;
    const int lb16 = (lane >> 4) & 1;
    const int lg = lane >> 2;
    const int tig = lane & 3;
    const int q0 = qt * 128;
    const int qb = w * 16;

    auto load_k = [&](int jt, int buf) {
        const size_t rowbase = (size_t)(jt * 64) * KV_D + kvg * HD;
#pragma unroll
        for (int i = 0; i < 8; i++) {
            int c = tid + i * 256;
            int plane = c >> 10;
            int idx = c & 1023;
            int row = idx >> 4;
            int ch = idx & 15;
            const __half* src = (plane ? Klf : Khf) + rowbase + (size_t)row * KV_D + ch * 8;
            cp_async16(smem_u32 + FK0 + buf * 34816 + plane * 17408 +
                       (row * QROW + ch * 8) * 2, src);
        }
    };
    auto load_v = [&](int jt, int buf) {
        const size_t rowbase = (size_t)(jt * 64) * KV_D + kvg * HD;
#pragma unroll
        for (int i = 0; i < 4; i++) {
            int c = tid + i * 256;
            int row = c >> 4;
            int ch = c & 15;
            const __half* src = Vf + rowbase + (size_t)row * KV_D + ch * 8;
            cp_async16(smem_u32 + FV0 + buf * FVSTG + (row * QROW + ch * 8) * 2, src);
        }
    };

    // Prologue
#pragma unroll
    for (int i = 0; i < 8; i++) {
        int c = tid + i * 256;
        int row = c >> 4;
        int ch = c & 15;
        const __half* src = Qf + (size_t)(q0 + row) * D_MODEL + h * HD + ch * 8;
        cp_async16(smem_u32 + (row * QROW + ch * 8) * 2, src);
    }
    load_k(0, 0);
    cp_async_commit();
    const int njt = 2 * qt + 2;
    load_k(1, 1);
    load_v(0, 0);
    cp_async_commit();

    const uint32_t qa = smem_u32 + ((qb + lb8 * 8 + lr) * QROW + lb16 * 8) * 2;
    const uint32_t k_off = ((lb16 * 8 + lr) * QROW + lb8 * 8) * 2;
    const uint32_t v_off = ((lb8 * 8 + lr) * QROW + lb16 * 8) * 2;

    float m0 = -1e30f, m1 = -1e30f, l0 = 0.0f, l1 = 0.0f;
    float oacc[16][4];
#pragma unroll
    for (int nt = 0; nt < 16; nt++)
#pragma unroll
        for (int j = 0; j < 4; j++) oacc[nt][j] = 0.0f;

    uint32_t pf[4][4];
    float ap0 = 1.0f, ap1 = 1.0f;
    int have_prev = 0;

    for (int jt = 0; jt < njt; jt++) {
        cp_async_wait<1>();
        __syncthreads();

        const uint32_t kb = smem_u32 + FK0 + (jt & 1) * 34816;
        const uint32_t vb_prev = smem_u32 + FV0 + ((jt & 1) ^ 1) * FVSTG;
        const bool active = (jt * 64 <= q0 + qb + 15);

        float sacc[8][4];
        if (active) {
#pragma unroll
            for (int nt = 0; nt < 8; nt++)
#pragma unroll
                for (int j = 0; j < 4; j++) sacc[nt][j] = 0.0f;

#pragma unroll
            for (int kc = 0; kc < 8; kc++) {
                uint32_t qf4[4];
                ldsm_x4(qf4, qa + kc * 32);
#pragma unroll
                for (int ntp = 0; ntp < 4; ntp++) {
                    uint32_t khf4[4], klf4[4];
                    uint32_t ka = kb + k_off + ntp * (16 * QROW * 2) + kc * 32;
                    ldsm_x4(khf4, ka);
                    ldsm_x4(klf4, ka + 17408);
                    mma_f16(sacc[2 * ntp], qf4, khf4);
                    mma_f16(sacc[2 * ntp], qf4, klf4);
                    mma_f16(sacc[2 * ntp + 1], qf4, khf4 + 2);
                    mma_f16(sacc[2 * ntp + 1], qf4, klf4 + 2);
                }
            }
        }

        // Deferred PV of previous tile
        if (have_prev) {
#pragma unroll
            for (int nt = 0; nt < 16; nt++) {
                oacc[nt][0] *= ap0;
                oacc[nt][1] *= ap0;
                oacc[nt][2] *= ap1;
                oacc[nt][3] *= ap1;
            }
#pragma unroll
            for (int kc = 0; kc < 4; kc++) {
#pragma unroll
                for (int ntp = 0; ntp < 8; ntp++) {
                    uint32_t vf4[4];
                    uint32_t va = vb_prev + v_off + kc * (16 * QROW * 2) + ntp * 32;
                    ldsm_x4t(vf4, va);
                    mma_f16(oacc[2 * ntp], pf[kc], vf4);
                    mma_f16(oacc[2 * ntp + 1], pf[kc], vf4 + 2);
                }
            }
            have_prev = 0;
        }

        if (active) {
            if (jt * 64 + 63 > q0 + qb) {
#pragma unroll
                for (int nt = 0; nt < 8; nt++)
#pragma unroll
                    for (int j = 0; j < 4; j++) {
                        int gj = jt * 64 + nt * 8 + tig * 2 + (j & 1);
                        int gi = q0 + qb + lg + ((j >> 1) << 3);
                        if (gj > gi) sacc[nt][j] = -1e30f;
                    }
            }

            float cur0 = -1e30f, cur1 = -1e30f;
#pragma unroll
            for (int nt = 0; nt < 8; nt++) {
                cur0 = fmaxf(cur0, fmaxf(sacc[nt][0], sacc[nt][1]));
                cur1 = fmaxf(cur1, fmaxf(sacc[nt][2], sacc[nt][3]));
            }
            cur0 = fmaxf(cur0, __shfl_xor_sync(0xffffffffu, cur0, 1));
            cur0 = fmaxf(cur0, __shfl_xor_sync(0xffffffffu, cur0, 2));
            cur1 = fmaxf(cur1, __shfl_xor_sync(0xffffffffu, cur1, 1));
            cur1 = fmaxf(cur1, __shfl_xor_sync(0xffffffffu, cur1, 2));

            float mn0 = fmaxf(m0, cur0), mn1 = fmaxf(m1, cur1);
            ap0 = __expf(m0 - mn0);
            ap1 = __expf(m1 - mn1);
            m0 = mn0; m1 = mn1;

            float rs0 = 0.0f, rs1 = 0.0f;
#pragma unroll
            for (int nt = 0; nt < 8; nt++) {
                sacc[nt][0] = __expf(sacc[nt][0] - mn0);
                sacc[nt][1] = __expf(sacc[nt][1] - mn0);
                sacc[nt][2] = __expf(sacc[nt][2] - mn1);
                sacc[nt][3] = __expf(sacc[nt][3] - mn1);
                rs0 += sacc[nt][0] + sacc[nt][1];
                rs1 += sacc[nt][2] + sacc[nt][3];
            }
            rs0 += __shfl_xor_sync(0xffffffffu, rs0, 1);
            rs0 += __shfl_xor_sync(0xffffffffu, rs0, 2);
            rs1 += __shfl_xor_sync(0xffffffffu, rs1, 1);
            rs1 += __shfl_xor_sync(0xffffffffu, rs1, 2);
            l0 = l0 * ap0 + rs0;
            l1 = l1 * ap1 + rs1;

#pragma unroll
            for (int kc = 0; kc < 4; kc++) {
                pf[kc][0] = pack_f16(sacc[2 * kc][0], sacc[2 * kc][1]);
                pf[kc][1] = pack_f16(sacc[2 * kc][2], sacc[2 * kc][3]);
                pf[kc][2] = pack_f16(sacc[2 * kc + 1][0], sacc[2 * kc + 1][1]);
                pf[kc][3] = pack_f16(sacc[2 * kc + 1][2], sacc[2 * kc + 1][3]);
            }
            have_prev = 1;
        }

        __syncthreads();
        if (jt + 2 < njt) load_k(jt + 2, jt & 1);
        if (jt + 1 < njt) load_v(jt + 1, (jt + 1) & 1);
        cp_async_commit();
    }

    // Final deferred PV
    cp_async_wait<0>();
    __syncthreads();
    if (have_prev) {
        const uint32_t vb_last = smem_u32 + FV0 + ((njt - 1) & 1) * FVSTG;
#pragma unroll
        for (int nt = 0; nt < 16; nt++) {
            oacc[nt][0] *= ap0;
            oacc[nt][1] *= ap0;
            oacc[nt][2] *= ap1;
            oacc[nt][3] *= ap1;
        }
#pragma unroll
        for (int kc = 0; kc < 4; kc++) {
#pragma unroll
            for (int ntp = 0; ntp < 8; ntp++) {
                uint32_t vf4[4];
                uint32_t va = vb_last + v_off + kc * (16 * QROW * 2) + ntp * 32;
                ldsm_x4t(vf4, va);
                mma_f16(oacc[2 * ntp], pf[kc], vf4);
                mma_f16(oacc[2 * ntp + 1], pf[kc], vf4 + 2);
            }
        }
    }

    float inv0 = 1.0f / l0;
    float inv1 = 1.0f / l1;
    int row0 = q0 + qb + lg;
    int row1 = row0 + 8;
#pragma unroll
    for (int nt = 0; nt < 16; nt++) {
        int col = h * HD + nt * 8 + tig * 2;
        *(uint32_t*)&Of[(size_t)row0 * D_MODEL + col] =
            pack_f16(oacc[nt][0] * inv0, oacc[nt][1] * inv0);
        *(uint32_t*)&Of[(size_t)row1 * D_MODEL + col] =
            pack_f16(oacc[nt][2] * inv1, oacc[nt][3] * inv1);
    }
}

// ---------------------------------------------------------------------------
extern "C" void kernel_launch(void* const* d_in, const int* in_sizes, int n_in,
                              void* d_out, int out_size) {
    const float* x    = (const float*)d_in[0];
    const float* wq   = (const float*)d_in[2];
    const float* wk   = (const float*)d_in[3];
    const float* wv   = (const float*)d_in[4];
    const float* wo   = (const float*)d_in[5];
    const float* cosp = (const float*)d_in[6];
    const float* sinp = (const float*)d_in[7];
    float* out = (float*)d_out;

    __half *xf, *qf, *khf, *klf, *vf, *ctxf, *wThf, *wTlf, *woThf, *woTlf;
    cudaGetSymbolAddress((void**)&xf, g_xf);
    cudaGetSymbolAddress((void**)&qf, g_qf);
    cudaGetSymbolAddress((void**)&khf, g_khf);
    cudaGetSymbolAddress((void**)&klf, g_klf);
    cudaGetSymbolAddress((void**)&vf, g_vf);
    cudaGetSymbolAddress((void**)&ctxf, g_ctxf);
    cudaGetSymbolAddress((void**)&wThf, g_wThf);
    cudaGetSymbolAddress((void**)&wTlf, g_wTlf);
    cudaGetSymbolAddress((void**)&woThf, g_woThf);
    cudaGetSymbolAddress((void**)&woTlf, g_woTlf);

    cudaFuncSetAttribute(gemm_f16_128, cudaFuncAttributeMaxDynamicSharedMemorySize, GM3_SMEM);
    cudaFuncSetAttribute(flash_attn_mma6, cudaFuncAttributeMaxDynamicSharedMemorySize, FB_SMEM);

    // x -> fp16; weights -> fp16 hi/lo (transposed, QKV concatenated)
    {
        int n4 = S_LEN * D_MODEL / 4;
        tofp16_kernel<<<(n4 + 255) / 256, 256>>>(x, xf, n4);
    }
    transpose_split_f16_kernel<<<dim3(D_MODEL / 32, D_MODEL / 32), dim3(32, 8)>>>(
        wq, wThf, wTlf, D_MODEL, D_MODEL);
    transpose_split_f16_kernel<<<dim3(KV_D / 32, D_MODEL / 32), dim3(32, 8)>>>(
        wk, wThf + (size_t)D_MODEL * D_MODEL, wTlf + (size_t)D_MODEL * D_MODEL, D_MODEL, KV_D);
    transpose_split_f16_kernel<<<dim3(KV_D / 32, D_MODEL / 32), dim3(32, 8)>>>(
        wv, wThf + (size_t)(D_MODEL + KV_D) * D_MODEL,
        wTlf + (size_t)(D_MODEL + KV_D) * D_MODEL, D_MODEL, KV_D);
    transpose_split_f16_kernel<<<dim3(D_MODEL / 32, D_MODEL / 32), dim3(32, 8)>>>(
        wo, woThf, woTlf, D_MODEL, D_MODEL);

    // Merged QKV projection (fp16 2-term)
    gemm_f16_128<<<dim3(QKV_N / 128, S_LEN / 128), 256, GM3_SMEM>>>(
        xf, wThf, wTlf, nullptr,
        qf, khf, klf, vf, cosp, sinp,
        S_LEN, QKV_N, D_MODEL);

    // Flash attention
    flash_attn_mma6<<<dim3((S_LEN / 128) * NH, 1), 256, FB_SMEM>>>(
        qf, khf, klf, vf, ctxf);

    // Output projection (fp16 2-term, fp32 out)
    gemm_f16_128<<<dim3(D_MODEL / 128, S_LEN / 128), 256, GM3_SMEM>>>(
        ctxf, woThf, woTlf, out,
        nullptr, nullptr, nullptr, nullptr, nullptr, nullptr,
        S_LEN, D_MODEL, D_MODEL);
}